// round 1
// baseline (speedup 1.0000x reference)
#include <cuda_runtime.h>

#define EMB   1024
#define T_SEQ 2048
#define BATCH 2
#define HEADS 16
#define HD    64
#define MROWS (BATCH * T_SEQ)   /* 4096 */
#define FF    (4 * EMB)         /* 4096 */

// -------------------- scratch (static device globals, no runtime alloc) ----
__device__ float g_h  [MROWS * EMB];
__device__ float g_q  [MROWS * EMB];   // [B,H,T,HD]
__device__ float g_k  [MROWS * EMB];
__device__ float g_v  [MROWS * EMB];
__device__ float g_att[MROWS * EMB];   // [B,T,C] (heads concatenated)
__device__ float g_x2 [MROWS * EMB];
__device__ float g_h2 [MROWS * EMB];
__device__ float g_u  [MROWS * FF];

// -------------------- LayerNorm: one block per row ------------------------
__global__ void __launch_bounds__(256) ln_kernel(
    const float* __restrict__ X, const float* __restrict__ gam,
    const float* __restrict__ bet, float* __restrict__ Y)
{
    const int row = blockIdx.x;
    const int tid = threadIdx.x;
    const float4 v = *reinterpret_cast<const float4*>(X + (size_t)row * EMB + tid * 4);
    float s  = v.x + v.y + v.z + v.w;
    float ss = v.x * v.x + v.y * v.y + v.z * v.z + v.w * v.w;
#pragma unroll
    for (int o = 16; o > 0; o >>= 1) {
        s  += __shfl_xor_sync(0xffffffffu, s,  o);
        ss += __shfl_xor_sync(0xffffffffu, ss, o);
    }
    __shared__ float sh_s[8], sh_ss[8];
    __shared__ float sh_mean, sh_r;
    const int wid = tid >> 5, lid = tid & 31;
    if (lid == 0) { sh_s[wid] = s; sh_ss[wid] = ss; }
    __syncthreads();
    if (tid == 0) {
        float ts = 0.f, tss = 0.f;
#pragma unroll
        for (int i = 0; i < 8; i++) { ts += sh_s[i]; tss += sh_ss[i]; }
        const float mean = ts * (1.0f / EMB);
        const float var  = tss * (1.0f / EMB) - mean * mean;
        sh_mean = mean;
        sh_r    = rsqrtf(var + 1e-5f);
    }
    __syncthreads();
    const float mean = sh_mean, r = sh_r;
    const float4 g4 = *reinterpret_cast<const float4*>(gam + tid * 4);
    const float4 b4 = *reinterpret_cast<const float4*>(bet + tid * 4);
    float4 y;
    y.x = (v.x - mean) * r * g4.x + b4.x;
    y.y = (v.y - mean) * r * g4.y + b4.y;
    y.z = (v.z - mean) * r * g4.z + b4.z;
    y.w = (v.w - mean) * r * g4.w + b4.w;
    *reinterpret_cast<float4*>(Y + (size_t)row * EMB + tid * 4) = y;
}

// -------------------- Tiled fp32 GEMM --------------------------------------
// C[M,N] = A[M,K] @ B[K,N]
// BLAYOUT 0: B row-major [K,N].
// BLAYOUT 1: head-blocked B: element (k,n) at B[(n/64)*K*64 + k*64 + (n%64)].
// EPI 0: plain store. EPI 1: scatter to [B,H,T,HD]. EPI 2: +bias[n] +res, store.
// EPI 3: +bias[n], relu, store.
template <int EPI, int BLAYOUT>
__global__ void __launch_bounds__(256) gemm_kernel(
    const float* __restrict__ A, const float* __restrict__ Bm,
    float* __restrict__ C, const float* __restrict__ bias,
    const float* __restrict__ res, int M, int N, int K)
{
    constexpr int BK = 32;
    __shared__ float As[BK][68];  // transposed tile: As[k][m], pad keeps 16B align
    __shared__ float Bs[BK][64];

    const int tid = threadIdx.x;
    const int tx  = tid & 15;       // 0..15 (n)
    const int ty  = tid >> 4;       // 0..15 (m)
    const int m0  = blockIdx.y * 64;
    const int n0  = blockIdx.x * 64;

    float acc[4][4] = {};

    for (int k0 = 0; k0 < K; k0 += BK) {
        // load A tile (64 x 32) transposed into As[k][m]
#pragma unroll
        for (int i = 0; i < 2; i++) {
            const int f  = tid + i * 256;     // float4 id, 0..511
            const int r  = f >> 3;            // row 0..63
            const int c4 = (f & 7) << 2;      // k offset 0..28
            const float4 a = *reinterpret_cast<const float4*>(
                &A[(size_t)(m0 + r) * K + k0 + c4]);
            As[c4 + 0][r] = a.x;
            As[c4 + 1][r] = a.y;
            As[c4 + 2][r] = a.z;
            As[c4 + 3][r] = a.w;
        }
        // load B tile (32 x 64)
#pragma unroll
        for (int i = 0; i < 2; i++) {
            const int f  = tid + i * 256;
            const int kk = f >> 4;            // 0..31
            const int n4 = (f & 15) << 2;     // 0..60
            const float* src;
            if (BLAYOUT == 0)
                src = &Bm[(size_t)(k0 + kk) * N + n0 + n4];
            else
                src = &Bm[(size_t)(n0 >> 6) * ((size_t)K * 64) + (size_t)(k0 + kk) * 64 + n4];
            *reinterpret_cast<float4*>(&Bs[kk][n4]) =
                *reinterpret_cast<const float4*>(src);
        }
        __syncthreads();
#pragma unroll
        for (int k = 0; k < BK; k++) {
            const float4 a4 = *reinterpret_cast<const float4*>(&As[k][ty * 4]);
            const float4 b4 = *reinterpret_cast<const float4*>(&Bs[k][tx * 4]);
            const float av[4] = {a4.x, a4.y, a4.z, a4.w};
            const float bv[4] = {b4.x, b4.y, b4.z, b4.w};
#pragma unroll
            for (int i = 0; i < 4; i++)
#pragma unroll
                for (int j = 0; j < 4; j++)
                    acc[i][j] += av[i] * bv[j];
        }
        __syncthreads();
    }

#pragma unroll
    for (int i = 0; i < 4; i++) {
        const int m = m0 + ty * 4 + i;
#pragma unroll
        for (int j = 0; j < 4; j++) {
            const int n = n0 + tx * 4 + j;
            float vv = acc[i][j];
            if (EPI == 0) {
                C[(size_t)m * N + n] = vv;
            } else if (EPI == 1) {
                const int bb = m >> 11, t = m & 2047, hh = n >> 6, d = n & 63;
                C[(((size_t)(bb * HEADS + hh)) * T_SEQ + t) * HD + d] = vv;
            } else if (EPI == 2) {
                C[(size_t)m * N + n] = vv + bias[n] + res[(size_t)m * N + n];
            } else {  // EPI == 3
                vv += bias[n];
                C[(size_t)m * N + n] = vv > 0.f ? vv : 0.f;
            }
        }
    }
}

// -------------------- Causal flash attention --------------------------------
// grid: (T/64, B*H), 64 threads. Thread owns one query row.
__global__ void __launch_bounds__(64) attn_kernel(
    const float* __restrict__ Q, const float* __restrict__ Kt,
    const float* __restrict__ Vt, float* __restrict__ Out)
{
    __shared__ float Ks[64][64];
    __shared__ float Vs[64][64];
    __shared__ float Ss[64][65];

    const int tid = threadIdx.x;
    const int bh  = blockIdx.y;
    const int t0  = blockIdx.x * 64;
    const int tq  = t0 + tid;
    const float scale = 0.03125f;  // 1024^-0.5

    float q[64], o[64];
    const float* qp = &Q[((size_t)bh * T_SEQ + tq) * HD];
#pragma unroll
    for (int d4 = 0; d4 < 16; d4++) {
        const float4 t = *reinterpret_cast<const float4*>(qp + d4 * 4);
        q[d4 * 4 + 0] = t.x * scale;
        q[d4 * 4 + 1] = t.y * scale;
        q[d4 * 4 + 2] = t.z * scale;
        q[d4 * 4 + 3] = t.w * scale;
    }
#pragma unroll
    for (int d = 0; d < 64; d++) o[d] = 0.f;

    float mval = -1e30f, l = 0.f;

    for (int j0 = 0; j0 <= t0; j0 += 64) {
        const float* kp = &Kt[((size_t)bh * T_SEQ + j0 + tid) * HD];
        const float* vp = &Vt[((size_t)bh * T_SEQ + j0 + tid) * HD];
#pragma unroll
        for (int d4 = 0; d4 < 16; d4++) {
            *reinterpret_cast<float4*>(&Ks[tid][d4 * 4]) =
                *reinterpret_cast<const float4*>(kp + d4 * 4);
            *reinterpret_cast<float4*>(&Vs[tid][d4 * 4]) =
                *reinterpret_cast<const float4*>(vp + d4 * 4);
        }
        __syncthreads();

        const int jmax = min(63, tq - j0);
        float tmax = -1e30f;
        for (int j = 0; j <= jmax; j++) {
            float s = 0.f;
#pragma unroll
            for (int d4 = 0; d4 < 16; d4++) {
                const float4 k4 = *reinterpret_cast<const float4*>(&Ks[j][d4 * 4]);
                s += q[d4 * 4 + 0] * k4.x + q[d4 * 4 + 1] * k4.y +
                     q[d4 * 4 + 2] * k4.z + q[d4 * 4 + 3] * k4.w;
            }
            Ss[tid][j] = s;
            tmax = fmaxf(tmax, s);
        }
        const float mnew = fmaxf(mval, tmax);
        const float corr = __expf(mval - mnew);
        l *= corr;
#pragma unroll
        for (int d = 0; d < 64; d++) o[d] *= corr;

        for (int j = 0; j <= jmax; j++) {
            const float p = __expf(Ss[tid][j] - mnew);
            l += p;
#pragma unroll
            for (int d4 = 0; d4 < 16; d4++) {
                const float4 v4 = *reinterpret_cast<const float4*>(&Vs[j][d4 * 4]);
                o[d4 * 4 + 0] += p * v4.x;
                o[d4 * 4 + 1] += p * v4.y;
                o[d4 * 4 + 2] += p * v4.z;
                o[d4 * 4 + 3] += p * v4.w;
            }
        }
        mval = mnew;
        __syncthreads();
    }

    const int b = bh >> 4, h = bh & 15;
    const float invl = 1.0f / l;
    float* op = &Out[((size_t)(b * T_SEQ + tq)) * EMB + h * HD];
#pragma unroll
    for (int d4 = 0; d4 < 16; d4++) {
        float4 y;
        y.x = o[d4 * 4 + 0] * invl;
        y.y = o[d4 * 4 + 1] * invl;
        y.z = o[d4 * 4 + 2] * invl;
        y.w = o[d4 * 4 + 3] * invl;
        *reinterpret_cast<float4*>(op + d4 * 4) = y;
    }
}

// -------------------- launch -------------------------------------------------
extern "C" void kernel_launch(void* const* d_in, const int* in_sizes, int n_in,
                              void* d_out, int out_size)
{
    const float* x   = (const float*)d_in[0];
    const float* wq  = (const float*)d_in[1];
    const float* wk  = (const float*)d_in[2];
    const float* wv  = (const float*)d_in[3];
    const float* wo  = (const float*)d_in[4];
    const float* bo  = (const float*)d_in[5];
    const float* g1  = (const float*)d_in[6];
    const float* b1  = (const float*)d_in[7];
    const float* g2  = (const float*)d_in[8];
    const float* b2  = (const float*)d_in[9];
    const float* w1  = (const float*)d_in[10];
    const float* bf1 = (const float*)d_in[11];
    const float* w2  = (const float*)d_in[12];
    const float* bf2 = (const float*)d_in[13];
    float* out = (float*)d_out;

    float *h, *q, *k, *v, *att, *x2, *h2, *u;
    cudaGetSymbolAddress((void**)&h,   g_h);
    cudaGetSymbolAddress((void**)&q,   g_q);
    cudaGetSymbolAddress((void**)&k,   g_k);
    cudaGetSymbolAddress((void**)&v,   g_v);
    cudaGetSymbolAddress((void**)&att, g_att);
    cudaGetSymbolAddress((void**)&x2,  g_x2);
    cudaGetSymbolAddress((void**)&h2,  g_h2);
    cudaGetSymbolAddress((void**)&u,   g_u);

    // LN1
    ln_kernel<<<MROWS, 256>>>(x, g1, b1, h);
    // QKV projections (head-blocked weights, scatter to [B,H,T,HD])
    gemm_kernel<1, 1><<<dim3(EMB / 64, MROWS / 64), 256>>>(h, wq, q, nullptr, nullptr, MROWS, EMB, EMB);
    gemm_kernel<1, 1><<<dim3(EMB / 64, MROWS / 64), 256>>>(h, wk, k, nullptr, nullptr, MROWS, EMB, EMB);
    gemm_kernel<1, 1><<<dim3(EMB / 64, MROWS / 64), 256>>>(h, wv, v, nullptr, nullptr, MROWS, EMB, EMB);
    // causal attention
    attn_kernel<<<dim3(T_SEQ / 64, BATCH * HEADS), 64>>>(q, k, v, att);
    // output projection + bias + residual(x)
    gemm_kernel<2, 0><<<dim3(EMB / 64, MROWS / 64), 256>>>(att, wo, x2, bo, x, MROWS, EMB, EMB);
    // LN2
    ln_kernel<<<MROWS, 256>>>(x2, g2, b2, h2);
    // FFN1 (+bias, relu)
    gemm_kernel<3, 0><<<dim3(FF / 64, MROWS / 64), 256>>>(h2, w1, u, bf1, nullptr, MROWS, FF, EMB);
    // FFN2 (+bias, +residual(x2)) -> final output
    gemm_kernel<2, 0><<<dim3(EMB / 64, MROWS / 64), 256>>>(u, w2, out, bf2, x2, MROWS, EMB, FF);
}

// round 4
// speedup vs baseline: 1.1757x; 1.1757x over previous
#include <cuda_runtime.h>
#include <cuda_bf16.h>
#include <cstdint>

#define EMB   1024
#define T_SEQ 2048
#define BATCH 2
#define HEADS 16
#define HD    64
#define MROWS (BATCH * T_SEQ)   /* 4096 */
#define FF    (4 * EMB)         /* 4096 */

// -------------------- scratch (static device globals) ----------------------
__device__ __nv_bfloat16 g_hh [MROWS * EMB];
__device__ __nv_bfloat16 g_hl [MROWS * EMB];
__device__ float         g_q  [MROWS * EMB];   // [B,H,T,HD]
__device__ float         g_k  [MROWS * EMB];
__device__ float         g_v  [MROWS * EMB];
__device__ __nv_bfloat16 g_ath[MROWS * EMB];   // attention out hi [B,T,C]
__device__ __nv_bfloat16 g_atl[MROWS * EMB];
__device__ float         g_x2 [MROWS * EMB];
__device__ __nv_bfloat16 g_h2h[MROWS * EMB];
__device__ __nv_bfloat16 g_h2l[MROWS * EMB];
__device__ __nv_bfloat16 g_uh [MROWS * FF];
__device__ __nv_bfloat16 g_ul [MROWS * FF];
// transposed+split weights [N,K]
__device__ __nv_bfloat16 g_wqh[EMB * EMB], g_wql[EMB * EMB];
__device__ __nv_bfloat16 g_wkh[EMB * EMB], g_wkl[EMB * EMB];
__device__ __nv_bfloat16 g_wvh[EMB * EMB], g_wvl[EMB * EMB];
__device__ __nv_bfloat16 g_woh[EMB * EMB], g_wol[EMB * EMB];
__device__ __nv_bfloat16 g_w1h[EMB * FF],  g_w1l[EMB * FF];
__device__ __nv_bfloat16 g_w2h[FF * EMB],  g_w2l[FF * EMB];

// -------------------- helpers ----------------------------------------------
__device__ __forceinline__ uint32_t smem_u32(const void* p) {
    uint32_t a;
    asm("{ .reg .u64 t; cvta.to.shared.u64 t, %1; cvt.u32.u64 %0, t; }" : "=r"(a) : "l"(p));
    return a;
}
__device__ __forceinline__ void cp16(uint32_t dst, const void* src) {
    asm volatile("cp.async.cg.shared.global [%0], [%1], 16;" :: "r"(dst), "l"(src) : "memory");
}
__device__ __forceinline__ void cp_commit() {
    asm volatile("cp.async.commit_group;" ::: "memory");
}
__device__ __forceinline__ void cp_wait1() {
    asm volatile("cp.async.wait_group 1;" ::: "memory");
}
__device__ __forceinline__ void ldsm4(uint32_t* r, uint32_t addr) {
    asm volatile("ldmatrix.sync.aligned.m8n8.x4.shared.b16 {%0,%1,%2,%3}, [%4];"
                 : "=r"(r[0]), "=r"(r[1]), "=r"(r[2]), "=r"(r[3]) : "r"(addr));
}
__device__ __forceinline__ void mma16816(float* d, const uint32_t* a, const uint32_t* b) {
    asm volatile(
        "mma.sync.aligned.m16n8k16.row.col.f32.bf16.bf16.f32 "
        "{%0,%1,%2,%3}, {%4,%5,%6,%7}, {%8,%9}, {%0,%1,%2,%3};"
        : "+f"(d[0]), "+f"(d[1]), "+f"(d[2]), "+f"(d[3])
        : "r"(a[0]), "r"(a[1]), "r"(a[2]), "r"(a[3]), "r"(b[0]), "r"(b[1]));
}

__device__ __forceinline__ void split_store(float a, float b,
                                            __nv_bfloat16* ph, __nv_bfloat16* pl) {
    __nv_bfloat16 ah = __float2bfloat16(a), bh = __float2bfloat16(b);
    __nv_bfloat16 al = __float2bfloat16(a - __bfloat162float(ah));
    __nv_bfloat16 bl = __float2bfloat16(b - __bfloat162float(bh));
    *reinterpret_cast<__nv_bfloat162*>(ph) = __nv_bfloat162(ah, bh);
    *reinterpret_cast<__nv_bfloat162*>(pl) = __nv_bfloat162(al, bl);
}

// -------------------- LayerNorm -> bf16 hi/lo -------------------------------
__global__ void __launch_bounds__(256) ln_split_kernel(
    const float* __restrict__ X, const float* __restrict__ gam,
    const float* __restrict__ bet, __nv_bfloat16* __restrict__ Yh,
    __nv_bfloat16* __restrict__ Yl)
{
    const int row = blockIdx.x;
    const int tid = threadIdx.x;
    const float4 v = *reinterpret_cast<const float4*>(X + (size_t)row * EMB + tid * 4);
    float s  = v.x + v.y + v.z + v.w;
    float ss = v.x * v.x + v.y * v.y + v.z * v.z + v.w * v.w;
#pragma unroll
    for (int o = 16; o > 0; o >>= 1) {
        s  += __shfl_xor_sync(0xffffffffu, s,  o);
        ss += __shfl_xor_sync(0xffffffffu, ss, o);
    }
    __shared__ float sh_s[8], sh_ss[8];
    __shared__ float sh_mean, sh_r;
    const int wid = tid >> 5, lid = tid & 31;
    if (lid == 0) { sh_s[wid] = s; sh_ss[wid] = ss; }
    __syncthreads();
    if (tid == 0) {
        float ts = 0.f, tss = 0.f;
#pragma unroll
        for (int i = 0; i < 8; i++) { ts += sh_s[i]; tss += sh_ss[i]; }
        const float mean = ts * (1.0f / EMB);
        const float var  = tss * (1.0f / EMB) - mean * mean;
        sh_mean = mean;
        sh_r    = rsqrtf(var + 1e-5f);
    }
    __syncthreads();
    const float mean = sh_mean, r = sh_r;
    const float4 g4 = *reinterpret_cast<const float4*>(gam + tid * 4);
    const float4 b4 = *reinterpret_cast<const float4*>(bet + tid * 4);
    float y0 = (v.x - mean) * r * g4.x + b4.x;
    float y1 = (v.y - mean) * r * g4.y + b4.y;
    float y2 = (v.z - mean) * r * g4.z + b4.z;
    float y3 = (v.w - mean) * r * g4.w + b4.w;
    const size_t o = (size_t)row * EMB + tid * 4;
    split_store(y0, y1, Yh + o, Yl + o);
    split_store(y2, y3, Yh + o + 2, Yl + o + 2);
}

// -------------------- weight transpose + split ------------------------------
// MODE 0: W row-major [K,N] -> out [N,K].
// MODE 1: W head-blocked [(n/64), K, (n%64)] -> out [N,K].
template <int MODE>
__global__ void __launch_bounds__(256) wsplit_kernel(
    const float* __restrict__ W, __nv_bfloat16* __restrict__ Wh,
    __nv_bfloat16* __restrict__ Wl, int K, int N)
{
    __shared__ float tile[32][33];
    const int tx = threadIdx.x & 31;
    const int ty = threadIdx.x >> 5;   // 0..7
    const int n0 = blockIdx.x * 32;
    const int k0 = blockIdx.y * 32;
#pragma unroll
    for (int r = 0; r < 4; r++) {
        const int k = k0 + ty + r * 8;
        const int n = n0 + tx;
        size_t idx;
        if (MODE == 0) idx = (size_t)k * N + n;
        else           idx = (((size_t)(n >> 6) * K + k) << 6) + (n & 63);
        tile[ty + r * 8][tx] = W[idx];
    }
    __syncthreads();
#pragma unroll
    for (int r = 0; r < 4; r++) {
        const int n = n0 + ty + r * 8;
        const int k = k0 + tx;
        const float v = tile[tx][ty + r * 8];
        __nv_bfloat16 h = __float2bfloat16(v);
        Wh[(size_t)n * K + k] = h;
        Wl[(size_t)n * K + k] = __float2bfloat16(v - __bfloat162float(h));
    }
}

// -------------------- mma.sync split-bf16 GEMM ------------------------------
// D[M,N] = A[M,K] * B[N,K]^T with A = Ah+Al, B = Bh+Bl (3 HMMA passes).
// EPI 0: scatter fp32 to [B,H,T,HD]. EPI 1: +bias +res -> fp32. EPI 2: relu(+bias) -> bf16 hi/lo.
#define RB    80            /* padded row bytes: 40 bf16 */
#define MATB  (128 * RB)    /* one matrix tile: 10240 B  */
#define STGB  (4 * MATB)    /* one stage: Ah,Al,Bh,Bl    */
#define GSMEM_BYTES (2 * STGB)

template <int EPI>
__global__ void __launch_bounds__(256, 1) mma_gemm(
    const __nv_bfloat16* __restrict__ Ah, const __nv_bfloat16* __restrict__ Al,
    const __nv_bfloat16* __restrict__ Bh, const __nv_bfloat16* __restrict__ Bl,
    float* __restrict__ Cf, __nv_bfloat16* __restrict__ Ch, __nv_bfloat16* __restrict__ Cl,
    const float* __restrict__ bias, const float* __restrict__ res,
    int M, int N, int K)
{
    extern __shared__ char smem[];
    const uint32_t sbase = smem_u32(smem);
    const int tid  = threadIdx.x;
    const int wid  = tid >> 5, lane = tid & 31;
    const int m0   = blockIdx.y * 128, n0 = blockIdx.x * 128;
    const int wm   = wid & 3;      // m sub-tile (32 rows)
    const int wn   = wid >> 2;     // n sub-tile (64 cols)

    // global load mapping: 256 threads cover 128 rows x 4 kgroups (16B each), x4 matrices
    const int lr  = tid & 127;
    const int kg2 = tid >> 7;                 // 0 -> kg {0,1}, 1 -> kg {2,3}
    const __nv_bfloat16* gAh = Ah + (size_t)(m0 + lr) * K;
    const __nv_bfloat16* gAl = Al + (size_t)(m0 + lr) * K;
    const __nv_bfloat16* gBh = Bh + (size_t)(n0 + lr) * K;
    const __nv_bfloat16* gBl = Bl + (size_t)(n0 + lr) * K;
    const uint32_t srow = sbase + lr * RB;

    float acc[2][8][4];
#pragma unroll
    for (int i = 0; i < 2; i++)
#pragma unroll
        for (int j = 0; j < 8; j++)
#pragma unroll
            for (int t = 0; t < 4; t++) acc[i][j][t] = 0.f;

    const int NC = K >> 5;

    // ldmatrix per-lane offsets
    const int arow  = wm * 32 + (lane & 15);                    // + mi*16
    const int akoff = (lane >> 4) * 8;                          // + ks*16
    const int brow  = wn * 64 + (lane & 7) + ((lane >> 4) << 3);// + nt*16
    const int bkoff = ((lane >> 3) & 1) * 8;                    // + ks*16

    // prefetch chunk 0
    {
        const uint32_t sd = srow;  // stage 0
#pragma unroll
        for (int g = 0; g < 2; g++) {
            const int kg = kg2 * 2 + g;
            const uint32_t o = sd + kg * 16;
            cp16(o,            gAh + kg * 8);
            cp16(o + MATB,     gAl + kg * 8);
            cp16(o + 2 * MATB, gBh + kg * 8);
            cp16(o + 3 * MATB, gBl + kg * 8);
        }
    }
    cp_commit();

    for (int c = 0; c < NC; c++) {
        if (c + 1 < NC) {
            const int k0 = (c + 1) * 32;
            const uint32_t sd = srow + ((c + 1) & 1) * STGB;
#pragma unroll
            for (int g = 0; g < 2; g++) {
                const int kg = kg2 * 2 + g;
                const uint32_t o = sd + kg * 16;
                cp16(o,            gAh + k0 + kg * 8);
                cp16(o + MATB,     gAl + k0 + kg * 8);
                cp16(o + 2 * MATB, gBh + k0 + kg * 8);
                cp16(o + 3 * MATB, gBl + k0 + kg * 8);
            }
        }
        cp_commit();
        cp_wait1();
        __syncthreads();

        const uint32_t sb = sbase + (c & 1) * STGB;
#pragma unroll
        for (int ks = 0; ks < 2; ks++) {
            uint32_t aH[2][4], aL[2][4], bH[4][4], bL[4][4];
#pragma unroll
            for (int mi = 0; mi < 2; mi++) {
                const uint32_t ad = sb + (arow + mi * 16) * RB + (ks * 16 + akoff) * 2;
                ldsm4(aH[mi], ad);
                ldsm4(aL[mi], ad + MATB);
            }
#pragma unroll
            for (int nt = 0; nt < 4; nt++) {
                const uint32_t bd = sb + 2 * MATB + (brow + nt * 16) * RB + (ks * 16 + bkoff) * 2;
                ldsm4(bH[nt], bd);
                ldsm4(bL[nt], bd + MATB);
            }
#pragma unroll
            for (int mi = 0; mi < 2; mi++)
#pragma unroll
                for (int nj = 0; nj < 8; nj++) {
                    const uint32_t* b_h = &bH[nj >> 1][(nj & 1) * 2];
                    const uint32_t* b_l = &bL[nj >> 1][(nj & 1) * 2];
                    mma16816(acc[mi][nj], aH[mi], b_h);
                    mma16816(acc[mi][nj], aH[mi], b_l);
                    mma16816(acc[mi][nj], aL[mi], b_h);
                }
        }
        __syncthreads();
    }

    // epilogue
    const int mrow = m0 + wm * 32 + (lane >> 2);
    const int ncol = n0 + wn * 64 + (lane & 3) * 2;
#pragma unroll
    for (int mi = 0; mi < 2; mi++)
#pragma unroll
        for (int nj = 0; nj < 8; nj++)
#pragma unroll
            for (int hf = 0; hf < 2; hf++) {
                const int m = mrow + mi * 16 + hf * 8;
                const int n = ncol + nj * 8;
                float v0 = acc[mi][nj][hf * 2 + 0];
                float v1 = acc[mi][nj][hf * 2 + 1];
                if (EPI == 0) {
                    const int bb = m >> 11, t = m & 2047, hh = n >> 6, d = n & 63;
                    float2 o = make_float2(v0, v1);
                    *reinterpret_cast<float2*>(
                        Cf + (((size_t)(bb * HEADS + hh)) * T_SEQ + t) * HD + d) = o;
                } else if (EPI == 1) {
                    const size_t base = (size_t)m * N + n;
                    const float2 bs = *reinterpret_cast<const float2*>(bias + n);
                    const float2 rs = *reinterpret_cast<const float2*>(res + base);
                    float2 o = make_float2(v0 + bs.x + rs.x, v1 + bs.y + rs.y);
                    *reinterpret_cast<float2*>(Cf + base) = o;
                } else {
                    const size_t base = (size_t)m * N + n;
                    const float2 bs = *reinterpret_cast<const float2*>(bias + n);
                    float a = fmaxf(v0 + bs.x, 0.f);
                    float b = fmaxf(v1 + bs.y, 0.f);
                    split_store(a, b, Ch + base, Cl + base);
                }
            }
}

// -------------------- causal flash attention (fp32, bf16-split output) ------
// grid (T/64, B*H), 128 threads: 2 threads per query row (HD halves).
#define ASMEM_BYTES ((64 * 64 + 64 * 64 + 64 * 65) * 4)
__global__ void __launch_bounds__(128) attn_kernel(
    const float* __restrict__ Q, const float* __restrict__ Kt,
    const float* __restrict__ Vt,
    __nv_bfloat16* __restrict__ Oh, __nv_bfloat16* __restrict__ Ol)
{
    extern __shared__ float sm[];
    float* Ks = sm;                // [64][64]
    float* Vs = sm + 64 * 64;      // [64][64]
    float* Ss = sm + 2 * 64 * 64;  // [64][65]

    const int tid  = threadIdx.x;
    const int row  = tid >> 1;
    const int half = tid & 1;
    const int lane = tid & 31;
    // pair mask: the 2 lanes sharing one query row (same loop trip count)
    const uint32_t pmask = 0x3u << (lane & 30);
    const int bh   = blockIdx.y;
    const int t0   = blockIdx.x * 64;
    const int tq   = t0 + row;
    const float scale = 0.03125f;  // 1024^-0.5

    float q[32], o[32];
    const float* qp = Q + ((size_t)bh * T_SEQ + tq) * HD + half * 32;
#pragma unroll
    for (int d4 = 0; d4 < 8; d4++) {
        const float4 t = *reinterpret_cast<const float4*>(qp + d4 * 4);
        q[d4 * 4 + 0] = t.x * scale;
        q[d4 * 4 + 1] = t.y * scale;
        q[d4 * 4 + 2] = t.z * scale;
        q[d4 * 4 + 3] = t.w * scale;
    }
#pragma unroll
    for (int d = 0; d < 32; d++) o[d] = 0.f;

    float mval = -1e30f, l = 0.f;

    for (int j0 = 0; j0 <= t0; j0 += 64) {
        const float* kp = Kt + ((size_t)bh * T_SEQ + j0 + row) * HD + half * 32;
        const float* vp = Vt + ((size_t)bh * T_SEQ + j0 + row) * HD + half * 32;
        float* ksd = Ks + row * 64 + half * 32;
        float* vsd = Vs + row * 64 + half * 32;
#pragma unroll
        for (int d4 = 0; d4 < 8; d4++) {
            *reinterpret_cast<float4*>(ksd + d4 * 4) =
                *reinterpret_cast<const float4*>(kp + d4 * 4);
            *reinterpret_cast<float4*>(vsd + d4 * 4) =
                *reinterpret_cast<const float4*>(vp + d4 * 4);
        }
        __syncthreads();

        const int jmax = min(63, tq - j0);
        float tmax = -1e30f;
        for (int j = 0; j <= jmax; j++) {
            const float* kr = Ks + j * 64 + half * 32;
            float s0 = 0.f, s1 = 0.f, s2 = 0.f, s3 = 0.f;
            {
                const float4 a = *reinterpret_cast<const float4*>(kr);
                const float4 b = *reinterpret_cast<const float4*>(kr + 4);
                const float4 c = *reinterpret_cast<const float4*>(kr + 8);
                const float4 d = *reinterpret_cast<const float4*>(kr + 12);
                s0 += q[0]*a.x + q[1]*a.y + q[2]*a.z + q[3]*a.w;
                s1 += q[4]*b.x + q[5]*b.y + q[6]*b.z + q[7]*b.w;
                s2 += q[8]*c.x + q[9]*c.y + q[10]*c.z + q[11]*c.w;
                s3 += q[12]*d.x + q[13]*d.y + q[14]*d.z + q[15]*d.w;
            }
            {
                const float4 a = *reinterpret_cast<const float4*>(kr + 16);
                const float4 b = *reinterpret_cast<const float4*>(kr + 20);
                const float4 c = *reinterpret_cast<const float4*>(kr + 24);
                const float4 d = *reinterpret_cast<const float4*>(kr + 28);
                s0 += q[16]*a.x + q[17]*a.y + q[18]*a.z + q[19]*a.w;
                s1 += q[20]*b.x + q[21]*b.y + q[22]*b.z + q[23]*b.w;
                s2 += q[24]*c.x + q[25]*c.y + q[26]*c.z + q[27]*c.w;
                s3 += q[28]*d.x + q[29]*d.y + q[30]*d.z + q[31]*d.w;
            }
            float s = (s0 + s1) + (s2 + s3);
            s += __shfl_xor_sync(pmask, s, 1);   // pair-only: same trip count
            if (half == 0) Ss[row * 65 + j] = s;
            tmax = fmaxf(tmax, s);
        }
        __syncwarp();
        const float mnew = fmaxf(mval, tmax);
        const float corr = __expf(mval - mnew);
        l *= corr;
#pragma unroll
        for (int d = 0; d < 32; d++) o[d] *= corr;

        for (int j = 0; j <= jmax; j++) {
            const float p = __expf(Ss[row * 65 + j] - mnew);
            l += p;
            const float* vr = Vs + j * 64 + half * 32;
#pragma unroll
            for (int d4 = 0; d4 < 8; d4++) {
                const float4 v4 = *reinterpret_cast<const float4*>(vr + d4 * 4);
                o[d4 * 4 + 0] += p * v4.x;
                o[d4 * 4 + 1] += p * v4.y;
                o[d4 * 4 + 2] += p * v4.z;
                o[d4 * 4 + 3] += p * v4.w;
            }
        }
        mval = mnew;
        __syncthreads();
    }

    const int b = bh >> 4, h = bh & 15;
    const float invl = 1.0f / l;
    const size_t obase = ((size_t)(b * T_SEQ + tq)) * EMB + h * HD + half * 32;
#pragma unroll
    for (int d = 0; d < 32; d += 2)
        split_store(o[d] * invl, o[d + 1] * invl, Oh + obase + d, Ol + obase + d);
}

// -------------------- launch -------------------------------------------------
extern "C" void kernel_launch(void* const* d_in, const int* in_sizes, int n_in,
                              void* d_out, int out_size)
{
    const float* x   = (const float*)d_in[0];
    const float* wq  = (const float*)d_in[1];
    const float* wk  = (const float*)d_in[2];
    const float* wv  = (const float*)d_in[3];
    const float* wo  = (const float*)d_in[4];
    const float* bo  = (const float*)d_in[5];
    const float* g1  = (const float*)d_in[6];
    const float* b1  = (const float*)d_in[7];
    const float* g2  = (const float*)d_in[8];
    const float* b2  = (const float*)d_in[9];
    const float* w1  = (const float*)d_in[10];
    const float* bf1 = (const float*)d_in[11];
    const float* w2  = (const float*)d_in[12];
    const float* bf2 = (const float*)d_in[13];
    float* out = (float*)d_out;

    cudaFuncSetAttribute(mma_gemm<0>, cudaFuncAttributeMaxDynamicSharedMemorySize, GSMEM_BYTES);
    cudaFuncSetAttribute(mma_gemm<1>, cudaFuncAttributeMaxDynamicSharedMemorySize, GSMEM_BYTES);
    cudaFuncSetAttribute(mma_gemm<2>, cudaFuncAttributeMaxDynamicSharedMemorySize, GSMEM_BYTES);
    cudaFuncSetAttribute(attn_kernel, cudaFuncAttributeMaxDynamicSharedMemorySize, ASMEM_BYTES);

    __nv_bfloat16 *hh, *hl, *ath, *atl, *h2h, *h2l, *uh, *ul;
    __nv_bfloat16 *wqh, *wql, *wkh, *wkl, *wvh, *wvl, *woh, *wol, *w1h, *w1l, *w2h, *w2l;
    float *q, *k, *v, *x2;
    cudaGetSymbolAddress((void**)&hh,  g_hh);  cudaGetSymbolAddress((void**)&hl,  g_hl);
    cudaGetSymbolAddress((void**)&q,   g_q);   cudaGetSymbolAddress((void**)&k,   g_k);
    cudaGetSymbolAddress((void**)&v,   g_v);
    cudaGetSymbolAddress((void**)&ath, g_ath); cudaGetSymbolAddress((void**)&atl, g_atl);
    cudaGetSymbolAddress((void**)&x2,  g_x2);
    cudaGetSymbolAddress((void**)&h2h, g_h2h); cudaGetSymbolAddress((void**)&h2l, g_h2l);
    cudaGetSymbolAddress((void**)&uh,  g_uh);  cudaGetSymbolAddress((void**)&ul,  g_ul);
    cudaGetSymbolAddress((void**)&wqh, g_wqh); cudaGetSymbolAddress((void**)&wql, g_wql);
    cudaGetSymbolAddress((void**)&wkh, g_wkh); cudaGetSymbolAddress((void**)&wkl, g_wkl);
    cudaGetSymbolAddress((void**)&wvh, g_wvh); cudaGetSymbolAddress((void**)&wvl, g_wvl);
    cudaGetSymbolAddress((void**)&woh, g_woh); cudaGetSymbolAddress((void**)&wol, g_wol);
    cudaGetSymbolAddress((void**)&w1h, g_w1h); cudaGetSymbolAddress((void**)&w1l, g_w1l);
    cudaGetSymbolAddress((void**)&w2h, g_w2h); cudaGetSymbolAddress((void**)&w2l, g_w2l);

    // weight prep (transpose + hi/lo split)
    wsplit_kernel<1><<<dim3(EMB / 32, EMB / 32), 256>>>(wq, wqh, wql, EMB, EMB);
    wsplit_kernel<1><<<dim3(EMB / 32, EMB / 32), 256>>>(wk, wkh, wkl, EMB, EMB);
    wsplit_kernel<1><<<dim3(EMB / 32, EMB / 32), 256>>>(wv, wvh, wvl, EMB, EMB);
    wsplit_kernel<0><<<dim3(EMB / 32, EMB / 32), 256>>>(wo, woh, wol, EMB, EMB);
    wsplit_kernel<0><<<dim3(FF  / 32, EMB / 32), 256>>>(w1, w1h, w1l, EMB, FF);
    wsplit_kernel<0><<<dim3(EMB / 32, FF  / 32), 256>>>(w2, w2h, w2l, FF,  EMB);

    // LN1 -> bf16 split
    ln_split_kernel<<<MROWS, 256>>>(x, g1, b1, hh, hl);
    // QKV projections (tensor cores), scatter fp32 to [B,H,T,HD]
    mma_gemm<0><<<dim3(EMB / 128, MROWS / 128), 256, GSMEM_BYTES>>>(
        hh, hl, wqh, wql, q, nullptr, nullptr, nullptr, nullptr, MROWS, EMB, EMB);
    mma_gemm<0><<<dim3(EMB / 128, MROWS / 128), 256, GSMEM_BYTES>>>(
        hh, hl, wkh, wkl, k, nullptr, nullptr, nullptr, nullptr, MROWS, EMB, EMB);
    mma_gemm<0><<<dim3(EMB / 128, MROWS / 128), 256, GSMEM_BYTES>>>(
        hh, hl, wvh, wvl, v, nullptr, nullptr, nullptr, nullptr, MROWS, EMB, EMB);
    // attention -> bf16 split [B,T,C]
    attn_kernel<<<dim3(T_SEQ / 64, BATCH * HEADS), 128, ASMEM_BYTES>>>(q, k, v, ath, atl);
    // out projection + bias + residual(x) -> x2 (fp32)
    mma_gemm<1><<<dim3(EMB / 128, MROWS / 128), 256, GSMEM_BYTES>>>(
        ath, atl, woh, wol, x2, nullptr, nullptr, bo, x, MROWS, EMB, EMB);
    // LN2 -> bf16 split
    ln_split_kernel<<<MROWS, 256>>>(x2, g2, b2, h2h, h2l);
    // FFN1: relu(h2 @ w1 + bf1) -> bf16 split
    mma_gemm<2><<<dim3(FF / 128, MROWS / 128), 256, GSMEM_BYTES>>>(
        h2h, h2l, w1h, w1l, nullptr, uh, ul, bf1, nullptr, MROWS, FF, EMB);
    // FFN2: u @ w2 + bf2 + x2 -> out (fp32)
    mma_gemm<1><<<dim3(EMB / 128, MROWS / 128), 256, GSMEM_BYTES>>>(
        uh, ul, w2h, w2l, out, nullptr, nullptr, bf2, x2, MROWS, EMB, FF);
}

// round 5
// speedup vs baseline: 2.8336x; 2.4102x over previous
#include <cuda_runtime.h>
#include <cuda_bf16.h>
#include <cstdint>

#define EMB   1024
#define T_SEQ 2048
#define BATCH 2
#define HEADS 16
#define HD    64
#define MROWS (BATCH * T_SEQ)   /* 4096 */
#define FF    (4 * EMB)         /* 4096 */

// -------------------- scratch (static device globals) ----------------------
__device__ __nv_bfloat16 g_hh [MROWS * EMB];
__device__ __nv_bfloat16 g_hl [MROWS * EMB];
__device__ __nv_bfloat16 g_q  [MROWS * EMB];   // [B,H,T,HD] bf16
__device__ __nv_bfloat16 g_k  [MROWS * EMB];
__device__ __nv_bfloat16 g_v  [MROWS * EMB];
__device__ __nv_bfloat16 g_at [MROWS * EMB];   // attention out [B,T,C] bf16
__device__ float         g_x2 [MROWS * EMB];
__device__ __nv_bfloat16 g_h2h[MROWS * EMB];
__device__ __nv_bfloat16 g_h2l[MROWS * EMB];
__device__ __nv_bfloat16 g_uh [MROWS * FF];
__device__ __nv_bfloat16 g_ul [MROWS * FF];
// transposed+split weights [N,K]
__device__ __nv_bfloat16 g_wqh[EMB * EMB], g_wql[EMB * EMB];
__device__ __nv_bfloat16 g_wkh[EMB * EMB], g_wkl[EMB * EMB];
__device__ __nv_bfloat16 g_wvh[EMB * EMB], g_wvl[EMB * EMB];
__device__ __nv_bfloat16 g_woh[EMB * EMB], g_wol[EMB * EMB];
__device__ __nv_bfloat16 g_w1h[EMB * FF],  g_w1l[EMB * FF];
__device__ __nv_bfloat16 g_w2h[FF * EMB],  g_w2l[FF * EMB];

// -------------------- helpers ----------------------------------------------
__device__ __forceinline__ uint32_t smem_u32(const void* p) {
    uint32_t a;
    asm("{ .reg .u64 t; cvta.to.shared.u64 t, %1; cvt.u32.u64 %0, t; }" : "=r"(a) : "l"(p));
    return a;
}
__device__ __forceinline__ void cp16(uint32_t dst, const void* src) {
    asm volatile("cp.async.cg.shared.global [%0], [%1], 16;" :: "r"(dst), "l"(src) : "memory");
}
__device__ __forceinline__ void cp_commit() {
    asm volatile("cp.async.commit_group;" ::: "memory");
}
__device__ __forceinline__ void cp_wait1() {
    asm volatile("cp.async.wait_group 1;" ::: "memory");
}
__device__ __forceinline__ void cp_wait0() {
    asm volatile("cp.async.wait_group 0;" ::: "memory");
}
__device__ __forceinline__ void ldsm4(uint32_t* r, uint32_t addr) {
    asm volatile("ldmatrix.sync.aligned.m8n8.x4.shared.b16 {%0,%1,%2,%3}, [%4];"
                 : "=r"(r[0]), "=r"(r[1]), "=r"(r[2]), "=r"(r[3]) : "r"(addr));
}
__device__ __forceinline__ void ldsm4t(uint32_t* r, uint32_t addr) {
    asm volatile("ldmatrix.sync.aligned.m8n8.x4.trans.shared.b16 {%0,%1,%2,%3}, [%4];"
                 : "=r"(r[0]), "=r"(r[1]), "=r"(r[2]), "=r"(r[3]) : "r"(addr));
}
__device__ __forceinline__ void mma16816(float* d, const uint32_t* a, const uint32_t* b) {
    asm volatile(
        "mma.sync.aligned.m16n8k16.row.col.f32.bf16.bf16.f32 "
        "{%0,%1,%2,%3}, {%4,%5,%6,%7}, {%8,%9}, {%0,%1,%2,%3};"
        : "+f"(d[0]), "+f"(d[1]), "+f"(d[2]), "+f"(d[3])
        : "r"(a[0]), "r"(a[1]), "r"(a[2]), "r"(a[3]), "r"(b[0]), "r"(b[1]));
}

__device__ __forceinline__ void split_store(float a, float b,
                                            __nv_bfloat16* ph, __nv_bfloat16* pl) {
    __nv_bfloat16 ah = __float2bfloat16(a), bh = __float2bfloat16(b);
    __nv_bfloat16 al = __float2bfloat16(a - __bfloat162float(ah));
    __nv_bfloat16 bl = __float2bfloat16(b - __bfloat162float(bh));
    *reinterpret_cast<__nv_bfloat162*>(ph) = __nv_bfloat162(ah, bh);
    *reinterpret_cast<__nv_bfloat162*>(pl) = __nv_bfloat162(al, bl);
}

// -------------------- LayerNorm -> bf16 hi/lo -------------------------------
__global__ void __launch_bounds__(256) ln_split_kernel(
    const float* __restrict__ X, const float* __restrict__ gam,
    const float* __restrict__ bet, __nv_bfloat16* __restrict__ Yh,
    __nv_bfloat16* __restrict__ Yl)
{
    const int row = blockIdx.x;
    const int tid = threadIdx.x;
    const float4 v = *reinterpret_cast<const float4*>(X + (size_t)row * EMB + tid * 4);
    float s  = v.x + v.y + v.z + v.w;
    float ss = v.x * v.x + v.y * v.y + v.z * v.z + v.w * v.w;
#pragma unroll
    for (int o = 16; o > 0; o >>= 1) {
        s  += __shfl_xor_sync(0xffffffffu, s,  o);
        ss += __shfl_xor_sync(0xffffffffu, ss, o);
    }
    __shared__ float sh_s[8], sh_ss[8];
    __shared__ float sh_mean, sh_r;
    const int wid = tid >> 5, lid = tid & 31;
    if (lid == 0) { sh_s[wid] = s; sh_ss[wid] = ss; }
    __syncthreads();
    if (tid == 0) {
        float ts = 0.f, tss = 0.f;
#pragma unroll
        for (int i = 0; i < 8; i++) { ts += sh_s[i]; tss += sh_ss[i]; }
        const float mean = ts * (1.0f / EMB);
        const float var  = tss * (1.0f / EMB) - mean * mean;
        sh_mean = mean;
        sh_r    = rsqrtf(var + 1e-5f);
    }
    __syncthreads();
    const float mean = sh_mean, r = sh_r;
    const float4 g4 = *reinterpret_cast<const float4*>(gam + tid * 4);
    const float4 b4 = *reinterpret_cast<const float4*>(bet + tid * 4);
    float y0 = (v.x - mean) * r * g4.x + b4.x;
    float y1 = (v.y - mean) * r * g4.y + b4.y;
    float y2 = (v.z - mean) * r * g4.z + b4.z;
    float y3 = (v.w - mean) * r * g4.w + b4.w;
    const size_t o = (size_t)row * EMB + tid * 4;
    split_store(y0, y1, Yh + o, Yl + o);
    split_store(y2, y3, Yh + o + 2, Yl + o + 2);
}

// -------------------- weight transpose + split ------------------------------
template <int MODE>
__global__ void __launch_bounds__(256) wsplit_kernel(
    const float* __restrict__ W, __nv_bfloat16* __restrict__ Wh,
    __nv_bfloat16* __restrict__ Wl, int K, int N)
{
    __shared__ float tile[32][33];
    const int tx = threadIdx.x & 31;
    const int ty = threadIdx.x >> 5;
    const int n0 = blockIdx.x * 32;
    const int k0 = blockIdx.y * 32;
#pragma unroll
    for (int r = 0; r < 4; r++) {
        const int k = k0 + ty + r * 8;
        const int n = n0 + tx;
        size_t idx;
        if (MODE == 0) idx = (size_t)k * N + n;
        else           idx = (((size_t)(n >> 6) * K + k) << 6) + (n & 63);
        tile[ty + r * 8][tx] = W[idx];
    }
    __syncthreads();
#pragma unroll
    for (int r = 0; r < 4; r++) {
        const int n = n0 + ty + r * 8;
        const int k = k0 + tx;
        const float v = tile[tx][ty + r * 8];
        __nv_bfloat16 h = __float2bfloat16(v);
        Wh[(size_t)n * K + k] = h;
        Wl[(size_t)n * K + k] = __float2bfloat16(v - __bfloat162float(h));
    }
}

// -------------------- mma.sync GEMM (NP=1 plain bf16, NP=3 hi/lo split) -----
// D[M,N] = A[M,K] * B[N,K]^T.
// EPI 0: bf16 scatter to [B,H,T,HD]. EPI 1: +bias +res -> fp32. EPI 2: relu(+bias) -> bf16 hi/lo.
#define RB    80
#define MATB  (128 * RB)
#define STGB  (4 * MATB)
#define GSMEM_BYTES (2 * STGB)

template <int EPI, int NP>
__global__ void __launch_bounds__(256, 1) mma_gemm(
    const __nv_bfloat16* __restrict__ Ah, const __nv_bfloat16* __restrict__ Al,
    const __nv_bfloat16* __restrict__ Bh, const __nv_bfloat16* __restrict__ Bl,
    float* __restrict__ Cf, __nv_bfloat16* __restrict__ Ch, __nv_bfloat16* __restrict__ Cl,
    const float* __restrict__ bias, const float* __restrict__ res,
    int M, int N, int K)
{
    extern __shared__ char smem[];
    const uint32_t sbase = smem_u32(smem);
    const int tid  = threadIdx.x;
    const int wid  = tid >> 5, lane = tid & 31;
    const int m0   = blockIdx.y * 128, n0 = blockIdx.x * 128;
    const int wm   = wid & 3;
    const int wn   = wid >> 2;

    const int lr  = tid & 127;
    const int kg2 = tid >> 7;
    const __nv_bfloat16* gAh = Ah + (size_t)(m0 + lr) * K;
    const __nv_bfloat16* gAl = (NP == 3) ? Al + (size_t)(m0 + lr) * K : nullptr;
    const __nv_bfloat16* gBh = Bh + (size_t)(n0 + lr) * K;
    const __nv_bfloat16* gBl = (NP == 3) ? Bl + (size_t)(n0 + lr) * K : nullptr;
    const uint32_t srow = sbase + lr * RB;

    float acc[2][8][4];
#pragma unroll
    for (int i = 0; i < 2; i++)
#pragma unroll
        for (int j = 0; j < 8; j++)
#pragma unroll
            for (int t = 0; t < 4; t++) acc[i][j][t] = 0.f;

    const int NC = K >> 5;

    const int arow  = wm * 32 + (lane & 15);
    const int akoff = (lane >> 4) * 8;
    const int brow  = wn * 64 + (lane & 7) + ((lane >> 4) << 3);
    const int bkoff = ((lane >> 3) & 1) * 8;

    // prefetch chunk 0
#pragma unroll
    for (int g = 0; g < 2; g++) {
        const int kg = kg2 * 2 + g;
        const uint32_t o = srow + kg * 16;
        cp16(o,            gAh + kg * 8);
        cp16(o + 2 * MATB, gBh + kg * 8);
        if (NP == 3) {
            cp16(o + MATB,     gAl + kg * 8);
            cp16(o + 3 * MATB, gBl + kg * 8);
        }
    }
    cp_commit();

    for (int c = 0; c < NC; c++) {
        if (c + 1 < NC) {
            const int k0 = (c + 1) * 32;
            const uint32_t sd = srow + ((c + 1) & 1) * STGB;
#pragma unroll
            for (int g = 0; g < 2; g++) {
                const int kg = kg2 * 2 + g;
                const uint32_t o = sd + kg * 16;
                cp16(o,            gAh + k0 + kg * 8);
                cp16(o + 2 * MATB, gBh + k0 + kg * 8);
                if (NP == 3) {
                    cp16(o + MATB,     gAl + k0 + kg * 8);
                    cp16(o + 3 * MATB, gBl + k0 + kg * 8);
                }
            }
            cp_commit();
            cp_wait1();
        } else {
            cp_wait0();
        }
        __syncthreads();

        const uint32_t sb = sbase + (c & 1) * STGB;
#pragma unroll
        for (int ks = 0; ks < 2; ks++) {
            uint32_t aH[2][4], aL[2][4], bH[4][4], bL[4][4];
#pragma unroll
            for (int mi = 0; mi < 2; mi++) {
                const uint32_t ad = sb + (arow + mi * 16) * RB + (ks * 16 + akoff) * 2;
                ldsm4(aH[mi], ad);
                if (NP == 3) ldsm4(aL[mi], ad + MATB);
            }
#pragma unroll
            for (int nt = 0; nt < 4; nt++) {
                const uint32_t bd = sb + 2 * MATB + (brow + nt * 16) * RB + (ks * 16 + bkoff) * 2;
                ldsm4(bH[nt], bd);
                if (NP == 3) ldsm4(bL[nt], bd + MATB);
            }
#pragma unroll
            for (int mi = 0; mi < 2; mi++)
#pragma unroll
                for (int nj = 0; nj < 8; nj++) {
                    const uint32_t* b_h = &bH[nj >> 1][(nj & 1) * 2];
                    mma16816(acc[mi][nj], aH[mi], b_h);
                    if (NP == 3) {
                        const uint32_t* b_l = &bL[nj >> 1][(nj & 1) * 2];
                        mma16816(acc[mi][nj], aH[mi], b_l);
                        mma16816(acc[mi][nj], aL[mi], b_h);
                    }
                }
        }
        __syncthreads();
    }

    // epilogue
    const int mrow = m0 + wm * 32 + (lane >> 2);
    const int ncol = n0 + wn * 64 + (lane & 3) * 2;
#pragma unroll
    for (int mi = 0; mi < 2; mi++)
#pragma unroll
        for (int nj = 0; nj < 8; nj++)
#pragma unroll
            for (int hf = 0; hf < 2; hf++) {
                const int m = mrow + mi * 16 + hf * 8;
                const int n = ncol + nj * 8;
                float v0 = acc[mi][nj][hf * 2 + 0];
                float v1 = acc[mi][nj][hf * 2 + 1];
                if (EPI == 0) {
                    const int bb = m >> 11, t = m & 2047, hh = n >> 6, d = n & 63;
                    *reinterpret_cast<__nv_bfloat162*>(
                        Ch + (((size_t)(bb * HEADS + hh)) * T_SEQ + t) * HD + d) =
                        __floats2bfloat162_rn(v0, v1);
                } else if (EPI == 1) {
                    const size_t base = (size_t)m * N + n;
                    const float2 bs = *reinterpret_cast<const float2*>(bias + n);
                    const float2 rs = *reinterpret_cast<const float2*>(res + base);
                    float2 o = make_float2(v0 + bs.x + rs.x, v1 + bs.y + rs.y);
                    *reinterpret_cast<float2*>(Cf + base) = o;
                } else {
                    const size_t base = (size_t)m * N + n;
                    const float2 bs = *reinterpret_cast<const float2*>(bias + n);
                    float a = fmaxf(v0 + bs.x, 0.f);
                    float b = fmaxf(v1 + bs.y, 0.f);
                    split_store(a, b, Ch + base, Cl + base);
                }
            }
}

// -------------------- tensor-core causal flash attention --------------------
// grid (T/64, B*H), 128 threads (4 warps, 16 q-rows each). All bf16 MMA.
#define KVROWB 144
#define QTILEB (64 * KVROWB)                 /* 9216 */
#define KVSTGB (2 * QTILEB)                  /* K+V per stage */
#define ATT_SMEM (QTILEB + 2 * KVSTGB)       /* 46080 */

__global__ void __launch_bounds__(128) attn_mma(
    const __nv_bfloat16* __restrict__ Qg, const __nv_bfloat16* __restrict__ Kg,
    const __nv_bfloat16* __restrict__ Vg, __nv_bfloat16* __restrict__ Og)
{
    extern __shared__ char sm[];
    const uint32_t sb = smem_u32(sm);
    const int tid = threadIdx.x, w = tid >> 5, lane = tid & 31;
    const int bh = blockIdx.y;
    const int t0 = blockIdx.x * 64;
    const int nc = blockIdx.x + 1;

    const int lrow = tid >> 1, lhalf = tid & 1;
    const size_t bhbase = (size_t)bh * T_SEQ;

    // Q tile (grouped with chunk 0)
    {
        const __nv_bfloat16* qs = Qg + (bhbase + t0 + lrow) * HD + lhalf * 32;
        const uint32_t qd = sb + lrow * KVROWB + lhalf * 64;
#pragma unroll
        for (int i = 0; i < 4; i++) cp16(qd + i * 16, qs + i * 8);
    }
    // K,V chunk 0
    {
        const __nv_bfloat16* ks = Kg + (bhbase + lrow) * HD + lhalf * 32;
        const __nv_bfloat16* vs = Vg + (bhbase + lrow) * HD + lhalf * 32;
        const uint32_t kd = sb + QTILEB + lrow * KVROWB + lhalf * 64;
#pragma unroll
        for (int i = 0; i < 4; i++) {
            cp16(kd + i * 16,          ks + i * 8);
            cp16(kd + QTILEB + i * 16, vs + i * 8);
        }
    }
    cp_commit();

    float o[8][4];
#pragma unroll
    for (int dn = 0; dn < 8; dn++)
#pragma unroll
        for (int t = 0; t < 4; t++) o[dn][t] = 0.f;
    float m1 = -1e30f, m2 = -1e30f, l1 = 0.f, l2 = 0.f;
    uint32_t qf[4][4];

    const int arow  = w * 16 + (lane & 15);
    const int akoff = (lane >> 4) * 8;
    const int brow  = (lane & 7) + ((lane >> 4) << 3);
    const int bkoff = ((lane >> 3) & 1) * 8;
    const int vrowo = (lane & 7) + 8 * ((lane >> 3) & 1);
    const int vcolo = 16 * (lane >> 4);

    for (int c = 0; c < nc; c++) {
        if (c + 1 < nc) {
            const int j0 = (c + 1) * 64;
            const __nv_bfloat16* ks = Kg + (bhbase + j0 + lrow) * HD + lhalf * 32;
            const __nv_bfloat16* vs = Vg + (bhbase + j0 + lrow) * HD + lhalf * 32;
            const uint32_t kd = sb + QTILEB + ((c + 1) & 1) * KVSTGB + lrow * KVROWB + lhalf * 64;
#pragma unroll
            for (int i = 0; i < 4; i++) {
                cp16(kd + i * 16,          ks + i * 8);
                cp16(kd + QTILEB + i * 16, vs + i * 8);
            }
            cp_commit();
            cp_wait1();
        } else {
            cp_wait0();
        }
        __syncthreads();

        if (c == 0) {
#pragma unroll
            for (int ks = 0; ks < 4; ks++)
                ldsm4(qf[ks], sb + arow * KVROWB + (ks * 16 + akoff) * 2);
        }
        const uint32_t kb = sb + QTILEB + (c & 1) * KVSTGB;
        const uint32_t vb = kb + QTILEB;

        // S = Q K^T
        float s[8][4];
#pragma unroll
        for (int nj = 0; nj < 8; nj++)
#pragma unroll
            for (int t = 0; t < 4; t++) s[nj][t] = 0.f;
#pragma unroll
        for (int ks = 0; ks < 4; ks++) {
            uint32_t bK[4][4];
#pragma unroll
            for (int nt = 0; nt < 4; nt++)
                ldsm4(bK[nt], kb + (nt * 16 + brow) * KVROWB + (ks * 16 + bkoff) * 2);
#pragma unroll
            for (int nj = 0; nj < 8; nj++)
                mma16816(s[nj], qf[ks], &bK[nj >> 1][(nj & 1) * 2]);
        }
        // scale (+ causal mask on diagonal chunk)
        const float sc = 0.03125f;  // 1024^-0.5
        if (c == nc - 1) {
            const int r1 = t0 + w * 16 + (lane >> 2);
#pragma unroll
            for (int nj = 0; nj < 8; nj++) {
                const int kvb = t0 + nj * 8 + 2 * (lane & 3);
                s[nj][0] = (kvb     <= r1    ) ? s[nj][0] * sc : -1e30f;
                s[nj][1] = (kvb + 1 <= r1    ) ? s[nj][1] * sc : -1e30f;
                s[nj][2] = (kvb     <= r1 + 8) ? s[nj][2] * sc : -1e30f;
                s[nj][3] = (kvb + 1 <= r1 + 8) ? s[nj][3] * sc : -1e30f;
            }
        } else {
#pragma unroll
            for (int nj = 0; nj < 8; nj++)
#pragma unroll
                for (int t = 0; t < 4; t++) s[nj][t] *= sc;
        }
        // row maxes (rows r and r+8)
        float mx1 = -1e30f, mx2 = -1e30f;
#pragma unroll
        for (int nj = 0; nj < 8; nj++) {
            mx1 = fmaxf(mx1, fmaxf(s[nj][0], s[nj][1]));
            mx2 = fmaxf(mx2, fmaxf(s[nj][2], s[nj][3]));
        }
        mx1 = fmaxf(mx1, __shfl_xor_sync(0xffffffffu, mx1, 1));
        mx1 = fmaxf(mx1, __shfl_xor_sync(0xffffffffu, mx1, 2));
        mx2 = fmaxf(mx2, __shfl_xor_sync(0xffffffffu, mx2, 1));
        mx2 = fmaxf(mx2, __shfl_xor_sync(0xffffffffu, mx2, 2));
        const float nm1 = fmaxf(m1, mx1), nm2 = fmaxf(m2, mx2);
        const float cor1 = __expf(m1 - nm1), cor2 = __expf(m2 - nm2);

        float ps1 = 0.f, ps2 = 0.f;
        uint32_t pf[4][4];
#pragma unroll
        for (int kk = 0; kk < 4; kk++) {
#pragma unroll
            for (int hf = 0; hf < 2; hf++) {
                const int nj = kk * 2 + hf;
                const float p0 = __expf(s[nj][0] - nm1);
                const float p1 = __expf(s[nj][1] - nm1);
                const float p2 = __expf(s[nj][2] - nm2);
                const float p3 = __expf(s[nj][3] - nm2);
                ps1 += p0 + p1;
                ps2 += p2 + p3;
                __nv_bfloat162 lo = __floats2bfloat162_rn(p0, p1);
                __nv_bfloat162 hi = __floats2bfloat162_rn(p2, p3);
                pf[kk][hf * 2 + 0] = *reinterpret_cast<uint32_t*>(&lo);
                pf[kk][hf * 2 + 1] = *reinterpret_cast<uint32_t*>(&hi);
            }
        }
        ps1 += __shfl_xor_sync(0xffffffffu, ps1, 1);
        ps1 += __shfl_xor_sync(0xffffffffu, ps1, 2);
        ps2 += __shfl_xor_sync(0xffffffffu, ps2, 1);
        ps2 += __shfl_xor_sync(0xffffffffu, ps2, 2);
        l1 = l1 * cor1 + ps1;
        l2 = l2 * cor2 + ps2;
#pragma unroll
        for (int dn = 0; dn < 8; dn++) {
            o[dn][0] *= cor1; o[dn][1] *= cor1;
            o[dn][2] *= cor2; o[dn][3] *= cor2;
        }
        m1 = nm1; m2 = nm2;

        // O += P V
#pragma unroll
        for (int kk = 0; kk < 4; kk++) {
            uint32_t bV[4][4];
            const uint32_t vr = vb + (kk * 16 + vrowo) * KVROWB + vcolo;
#pragma unroll
            for (int d16 = 0; d16 < 4; d16++)
                ldsm4t(bV[d16], vr + d16 * 32);
#pragma unroll
            for (int dn = 0; dn < 8; dn++)
                mma16816(o[dn], pf[kk], &bV[dn >> 1][(dn & 1) * 2]);
        }
        __syncthreads();
    }

    // write output [B,T,C] bf16
    const int b = bh >> 4, h = bh & 15;
    const float i1 = 1.f / l1, i2 = 1.f / l2;
    const int r1 = t0 + w * 16 + (lane >> 2);
    __nv_bfloat16* o1 = Og + ((size_t)(b * T_SEQ) + r1) * EMB + h * HD + 2 * (lane & 3);
    __nv_bfloat16* o2 = o1 + (size_t)8 * EMB;
#pragma unroll
    for (int dn = 0; dn < 8; dn++) {
        *reinterpret_cast<__nv_bfloat162*>(o1 + dn * 8) =
            __floats2bfloat162_rn(o[dn][0] * i1, o[dn][1] * i1);
        *reinterpret_cast<__nv_bfloat162*>(o2 + dn * 8) =
            __floats2bfloat162_rn(o[dn][2] * i2, o[dn][3] * i2);
    }
}

// -------------------- launch -------------------------------------------------
extern "C" void kernel_launch(void* const* d_in, const int* in_sizes, int n_in,
                              void* d_out, int out_size)
{
    const float* x   = (const float*)d_in[0];
    const float* wq  = (const float*)d_in[1];
    const float* wk  = (const float*)d_in[2];
    const float* wv  = (const float*)d_in[3];
    const float* wo  = (const float*)d_in[4];
    const float* bo  = (const float*)d_in[5];
    const float* g1  = (const float*)d_in[6];
    const float* b1  = (const float*)d_in[7];
    const float* g2  = (const float*)d_in[8];
    const float* b2  = (const float*)d_in[9];
    const float* w1  = (const float*)d_in[10];
    const float* bf1 = (const float*)d_in[11];
    const float* w2  = (const float*)d_in[12];
    const float* bf2 = (const float*)d_in[13];
    float* out = (float*)d_out;

    cudaFuncSetAttribute(mma_gemm<0,1>, cudaFuncAttributeMaxDynamicSharedMemorySize, GSMEM_BYTES);
    cudaFuncSetAttribute(mma_gemm<1,1>, cudaFuncAttributeMaxDynamicSharedMemorySize, GSMEM_BYTES);
    cudaFuncSetAttribute(mma_gemm<1,3>, cudaFuncAttributeMaxDynamicSharedMemorySize, GSMEM_BYTES);
    cudaFuncSetAttribute(mma_gemm<2,3>, cudaFuncAttributeMaxDynamicSharedMemorySize, GSMEM_BYTES);
    cudaFuncSetAttribute(attn_mma, cudaFuncAttributeMaxDynamicSharedMemorySize, ATT_SMEM);

    __nv_bfloat16 *hh, *hl, *qb, *kb, *vb, *at, *h2h, *h2l, *uh, *ul;
    __nv_bfloat16 *wqh, *wql, *wkh, *wkl, *wvh, *wvl, *woh, *wol, *w1h, *w1l, *w2h, *w2l;
    float *x2;
    cudaGetSymbolAddress((void**)&hh,  g_hh);  cudaGetSymbolAddress((void**)&hl,  g_hl);
    cudaGetSymbolAddress((void**)&qb,  g_q);   cudaGetSymbolAddress((void**)&kb,  g_k);
    cudaGetSymbolAddress((void**)&vb,  g_v);
    cudaGetSymbolAddress((void**)&at,  g_at);
    cudaGetSymbolAddress((void**)&x2,  g_x2);
    cudaGetSymbolAddress((void**)&h2h, g_h2h); cudaGetSymbolAddress((void**)&h2l, g_h2l);
    cudaGetSymbolAddress((void**)&uh,  g_uh);  cudaGetSymbolAddress((void**)&ul,  g_ul);
    cudaGetSymbolAddress((void**)&wqh, g_wqh); cudaGetSymbolAddress((void**)&wql, g_wql);
    cudaGetSymbolAddress((void**)&wkh, g_wkh); cudaGetSymbolAddress((void**)&wkl, g_wkl);
    cudaGetSymbolAddress((void**)&wvh, g_wvh); cudaGetSymbolAddress((void**)&wvl, g_wvl);
    cudaGetSymbolAddress((void**)&woh, g_woh); cudaGetSymbolAddress((void**)&wol, g_wol);
    cudaGetSymbolAddress((void**)&w1h, g_w1h); cudaGetSymbolAddress((void**)&w1l, g_w1l);
    cudaGetSymbolAddress((void**)&w2h, g_w2h); cudaGetSymbolAddress((void**)&w2l, g_w2l);

    // weight prep
    wsplit_kernel<1><<<dim3(EMB / 32, EMB / 32), 256>>>(wq, wqh, wql, EMB, EMB);
    wsplit_kernel<1><<<dim3(EMB / 32, EMB / 32), 256>>>(wk, wkh, wkl, EMB, EMB);
    wsplit_kernel<1><<<dim3(EMB / 32, EMB / 32), 256>>>(wv, wvh, wvl, EMB, EMB);
    wsplit_kernel<0><<<dim3(EMB / 32, EMB / 32), 256>>>(wo, woh, wol, EMB, EMB);
    wsplit_kernel<0><<<dim3(FF  / 32, EMB / 32), 256>>>(w1, w1h, w1l, EMB, FF);
    wsplit_kernel<0><<<dim3(EMB / 32, FF  / 32), 256>>>(w2, w2h, w2l, FF,  EMB);

    // LN1 -> bf16 (hi used by QKV single-pass)
    ln_split_kernel<<<MROWS, 256>>>(x, g1, b1, hh, hl);
    // QKV projections: single-pass bf16, bf16 scatter to [B,H,T,HD]
    mma_gemm<0,1><<<dim3(EMB / 128, MROWS / 128), 256, GSMEM_BYTES>>>(
        hh, nullptr, wqh, nullptr, nullptr, qb, nullptr, nullptr, nullptr, MROWS, EMB, EMB);
    mma_gemm<0,1><<<dim3(EMB / 128, MROWS / 128), 256, GSMEM_BYTES>>>(
        hh, nullptr, wkh, nullptr, nullptr, kb, nullptr, nullptr, nullptr, MROWS, EMB, EMB);
    mma_gemm<0,1><<<dim3(EMB / 128, MROWS / 128), 256, GSMEM_BYTES>>>(
        hh, nullptr, wvh, nullptr, nullptr, vb, nullptr, nullptr, nullptr, MROWS, EMB, EMB);
    // tensor-core flash attention -> bf16 [B,T,C]
    attn_mma<<<dim3(T_SEQ / 64, BATCH * HEADS), 128, ATT_SMEM>>>(qb, kb, vb, at);
    // out projection (single-pass) + bias + residual(x) -> x2 fp32
    mma_gemm<1,1><<<dim3(EMB / 128, MROWS / 128), 256, GSMEM_BYTES>>>(
        at, nullptr, woh, nullptr, x2, nullptr, nullptr, bo, x, MROWS, EMB, EMB);
    // LN2 -> bf16 hi/lo
    ln_split_kernel<<<MROWS, 256>>>(x2, g2, b2, h2h, h2l);
    // FFN1 (3-pass split): relu(h2 @ w1 + bf1) -> bf16 hi/lo
    mma_gemm<2,3><<<dim3(FF / 128, MROWS / 128), 256, GSMEM_BYTES>>>(
        h2h, h2l, w1h, w1l, nullptr, uh, ul, bf1, nullptr, MROWS, FF, EMB);
    // FFN2 (3-pass split): u @ w2 + bf2 + x2 -> out fp32
    mma_gemm<1,3><<<dim3(EMB / 128, MROWS / 128), 256, GSMEM_BYTES>>>(
        uh, ul, w2h, w2l, out, nullptr, nullptr, bf2, x2, MROWS, EMB, FF);
}

// round 6
// speedup vs baseline: 4.5326x; 1.5996x over previous
#include <cuda_runtime.h>
#include <cuda_fp16.h>
#include <cstdint>

#define EMB   1024
#define T_SEQ 2048
#define BATCH 2
#define HEADS 16
#define HD    64
#define MROWS (BATCH * T_SEQ)   /* 4096 */
#define FF    (4 * EMB)         /* 4096 */

// -------------------- scratch (static device globals) ----------------------
__device__ __half g_h  [MROWS * EMB];           // LN1 out fp16
__device__ __half g_qkv[3 * MROWS * EMB];       // q,k,v [3][B,H,T,HD]
__device__ __half g_at [MROWS * EMB];           // attention out [B,T,C]
__device__ float  g_x2 [MROWS * EMB];
__device__ __half g_h2 [MROWS * EMB];           // LN2 out fp16
__device__ __half g_u  [MROWS * FF];            // FFN1 out fp16
// transposed fp16 weights [N,K]
__device__ __half g_wqkv[3 * EMB * EMB];
__device__ __half g_wo  [EMB * EMB];
__device__ __half g_w1  [EMB * FF];
__device__ __half g_w2  [FF * EMB];

// -------------------- helpers ----------------------------------------------
__device__ __forceinline__ uint32_t smem_u32(const void* p) {
    uint32_t a;
    asm("{ .reg .u64 t; cvta.to.shared.u64 t, %1; cvt.u32.u64 %0, t; }" : "=r"(a) : "l"(p));
    return a;
}
__device__ __forceinline__ void cp16(uint32_t dst, const void* src) {
    asm volatile("cp.async.cg.shared.global [%0], [%1], 16;" :: "r"(dst), "l"(src) : "memory");
}
__device__ __forceinline__ void cp_commit() {
    asm volatile("cp.async.commit_group;" ::: "memory");
}
__device__ __forceinline__ void cp_wait1() {
    asm volatile("cp.async.wait_group 1;" ::: "memory");
}
__device__ __forceinline__ void cp_wait0() {
    asm volatile("cp.async.wait_group 0;" ::: "memory");
}
__device__ __forceinline__ void ldsm4(uint32_t* r, uint32_t addr) {
    asm volatile("ldmatrix.sync.aligned.m8n8.x4.shared.b16 {%0,%1,%2,%3}, [%4];"
                 : "=r"(r[0]), "=r"(r[1]), "=r"(r[2]), "=r"(r[3]) : "r"(addr));
}
__device__ __forceinline__ void ldsm4t(uint32_t* r, uint32_t addr) {
    asm volatile("ldmatrix.sync.aligned.m8n8.x4.trans.shared.b16 {%0,%1,%2,%3}, [%4];"
                 : "=r"(r[0]), "=r"(r[1]), "=r"(r[2]), "=r"(r[3]) : "r"(addr));
}
__device__ __forceinline__ void mma16816(float* d, const uint32_t* a, const uint32_t* b) {
    asm volatile(
        "mma.sync.aligned.m16n8k16.row.col.f32.f16.f16.f32 "
        "{%0,%1,%2,%3}, {%4,%5,%6,%7}, {%8,%9}, {%0,%1,%2,%3};"
        : "+f"(d[0]), "+f"(d[1]), "+f"(d[2]), "+f"(d[3])
        : "r"(a[0]), "r"(a[1]), "r"(a[2]), "r"(a[3]), "r"(b[0]), "r"(b[1]));
}

// -------------------- LayerNorm -> fp16 --------------------------------------
__global__ void __launch_bounds__(256) ln_h_kernel(
    const float* __restrict__ X, const float* __restrict__ gam,
    const float* __restrict__ bet, __half* __restrict__ Y)
{
    const int row = blockIdx.x;
    const int tid = threadIdx.x;
    const float4 v = *reinterpret_cast<const float4*>(X + (size_t)row * EMB + tid * 4);
    float s  = v.x + v.y + v.z + v.w;
    float ss = v.x * v.x + v.y * v.y + v.z * v.z + v.w * v.w;
#pragma unroll
    for (int o = 16; o > 0; o >>= 1) {
        s  += __shfl_xor_sync(0xffffffffu, s,  o);
        ss += __shfl_xor_sync(0xffffffffu, ss, o);
    }
    __shared__ float sh_s[8], sh_ss[8];
    __shared__ float sh_mean, sh_r;
    const int wid = tid >> 5, lid = tid & 31;
    if (lid == 0) { sh_s[wid] = s; sh_ss[wid] = ss; }
    __syncthreads();
    if (tid == 0) {
        float ts = 0.f, tss = 0.f;
#pragma unroll
        for (int i = 0; i < 8; i++) { ts += sh_s[i]; tss += sh_ss[i]; }
        const float mean = ts * (1.0f / EMB);
        const float var  = tss * (1.0f / EMB) - mean * mean;
        sh_mean = mean;
        sh_r    = rsqrtf(var + 1e-5f);
    }
    __syncthreads();
    const float mean = sh_mean, r = sh_r;
    const float4 g4 = *reinterpret_cast<const float4*>(gam + tid * 4);
    const float4 b4 = *reinterpret_cast<const float4*>(bet + tid * 4);
    const size_t o = (size_t)row * EMB + tid * 4;
    *reinterpret_cast<__half2*>(Y + o) = __floats2half2_rn(
        (v.x - mean) * r * g4.x + b4.x, (v.y - mean) * r * g4.y + b4.y);
    *reinterpret_cast<__half2*>(Y + o + 2) = __floats2half2_rn(
        (v.z - mean) * r * g4.z + b4.z, (v.w - mean) * r * g4.w + b4.w);
}

// -------------------- weight transpose to fp16 [N,K] -------------------------
// MODE 0: W row-major [K,N]. MODE 1: head-blocked [(n/64), K, (n%64)].
template <int MODE>
__global__ void __launch_bounds__(256) wtr_kernel(
    const float* __restrict__ W, __half* __restrict__ Wh, int K, int N)
{
    __shared__ float tile[32][33];
    const int tx = threadIdx.x & 31;
    const int ty = threadIdx.x >> 5;
    const int n0 = blockIdx.x * 32;
    const int k0 = blockIdx.y * 32;
#pragma unroll
    for (int r = 0; r < 4; r++) {
        const int k = k0 + ty + r * 8;
        const int n = n0 + tx;
        size_t idx;
        if (MODE == 0) idx = (size_t)k * N + n;
        else           idx = (((size_t)(n >> 6) * K + k) << 6) + (n & 63);
        tile[ty + r * 8][tx] = W[idx];
    }
    __syncthreads();
#pragma unroll
    for (int r = 0; r < 4; r++) {
        const int n = n0 + ty + r * 8;
        const int k = k0 + tx;
        Wh[(size_t)n * K + k] = __float2half(tile[tx][ty + r * 8]);
    }
}

// -------------------- mma.sync fp16 GEMM -------------------------------------
// D[M,N] = A[M,K] * B[N,K]^T.
// EPI 0: fp16 scatter to [3][B,H,T,HD]. EPI 1: +bias +res -> fp32. EPI 2: relu(+bias) -> fp16.
#define RB    80
#define MATB  (128 * RB)
#define STGB  (2 * MATB)
#define GSMEM_BYTES (2 * STGB)

template <int EPI>
__global__ void __launch_bounds__(256, 1) mma_gemm(
    const __half* __restrict__ A, const __half* __restrict__ B,
    float* __restrict__ Cf, __half* __restrict__ Chp,
    const float* __restrict__ bias, const float* __restrict__ res,
    int M, int N, int K)
{
    extern __shared__ char smem[];
    const uint32_t sbase = smem_u32(smem);
    const int tid  = threadIdx.x;
    const int wid  = tid >> 5, lane = tid & 31;
    const int m0   = blockIdx.y * 128, n0 = blockIdx.x * 128;
    const int wm   = wid & 3;
    const int wn   = wid >> 2;

    const int lr  = tid & 127;
    const int kg2 = tid >> 7;
    const __half* gA = A + (size_t)(m0 + lr) * K;
    const __half* gB = B + (size_t)(n0 + lr) * K;
    const uint32_t srow = sbase + lr * RB;

    float acc[2][8][4];
#pragma unroll
    for (int i = 0; i < 2; i++)
#pragma unroll
        for (int j = 0; j < 8; j++)
#pragma unroll
            for (int t = 0; t < 4; t++) acc[i][j][t] = 0.f;

    const int NC = K >> 5;

    const int arow  = wm * 32 + (lane & 15);
    const int akoff = (lane >> 4) * 8;
    const int brow  = wn * 64 + (lane & 7) + ((lane >> 4) << 3);
    const int bkoff = ((lane >> 3) & 1) * 8;

    // prefetch chunk 0
#pragma unroll
    for (int g = 0; g < 2; g++) {
        const int kg = kg2 * 2 + g;
        const uint32_t o = srow + kg * 16;
        cp16(o,        gA + kg * 8);
        cp16(o + MATB, gB + kg * 8);
    }
    cp_commit();

    for (int c = 0; c < NC; c++) {
        if (c + 1 < NC) {
            const int k0 = (c + 1) * 32;
            const uint32_t sd = srow + ((c + 1) & 1) * STGB;
#pragma unroll
            for (int g = 0; g < 2; g++) {
                const int kg = kg2 * 2 + g;
                const uint32_t o = sd + kg * 16;
                cp16(o,        gA + k0 + kg * 8);
                cp16(o + MATB, gB + k0 + kg * 8);
            }
            cp_commit();
            cp_wait1();
        } else {
            cp_wait0();
        }
        __syncthreads();

        const uint32_t sb = sbase + (c & 1) * STGB;
#pragma unroll
        for (int ks = 0; ks < 2; ks++) {
            uint32_t af[2][4], bf[4][4];
#pragma unroll
            for (int mi = 0; mi < 2; mi++)
                ldsm4(af[mi], sb + (arow + mi * 16) * RB + (ks * 16 + akoff) * 2);
#pragma unroll
            for (int nt = 0; nt < 4; nt++)
                ldsm4(bf[nt], sb + MATB + (brow + nt * 16) * RB + (ks * 16 + bkoff) * 2);
#pragma unroll
            for (int mi = 0; mi < 2; mi++)
#pragma unroll
                for (int nj = 0; nj < 8; nj++)
                    mma16816(acc[mi][nj], af[mi], &bf[nj >> 1][(nj & 1) * 2]);
        }
        __syncthreads();
    }

    // epilogue
    const int mrow = m0 + wm * 32 + (lane >> 2);
    const int ncol = n0 + wn * 64 + (lane & 3) * 2;
#pragma unroll
    for (int mi = 0; mi < 2; mi++)
#pragma unroll
        for (int nj = 0; nj < 8; nj++)
#pragma unroll
            for (int hf = 0; hf < 2; hf++) {
                const int m = mrow + mi * 16 + hf * 8;
                const int n = ncol + nj * 8;
                float v0 = acc[mi][nj][hf * 2 + 0];
                float v1 = acc[mi][nj][hf * 2 + 1];
                if (EPI == 0) {
                    const int mat = n >> 10, hh = (n >> 6) & 15, d = n & 63;
                    const int bb = m >> 11, t = m & 2047;
                    *reinterpret_cast<__half2*>(
                        Chp + (size_t)mat * (MROWS * EMB) +
                        (((size_t)(bb * HEADS + hh)) * T_SEQ + t) * HD + d) =
                        __floats2half2_rn(v0, v1);
                } else if (EPI == 1) {
                    const size_t base = (size_t)m * N + n;
                    const float2 bs = *reinterpret_cast<const float2*>(bias + n);
                    const float2 rs = *reinterpret_cast<const float2*>(res + base);
                    *reinterpret_cast<float2*>(Cf + base) =
                        make_float2(v0 + bs.x + rs.x, v1 + bs.y + rs.y);
                } else {
                    const size_t base = (size_t)m * N + n;
                    const float2 bs = *reinterpret_cast<const float2*>(bias + n);
                    *reinterpret_cast<__half2*>(Chp + base) =
                        __floats2half2_rn(fmaxf(v0 + bs.x, 0.f), fmaxf(v1 + bs.y, 0.f));
                }
            }
}

// -------------------- tensor-core causal flash attention (fp16) -------------
#define KVROWB 144
#define QTILEB (64 * KVROWB)
#define KVSTGB (2 * QTILEB)
#define ATT_SMEM (QTILEB + 2 * KVSTGB)

__global__ void __launch_bounds__(128) attn_mma(
    const __half* __restrict__ Qg, const __half* __restrict__ Kg,
    const __half* __restrict__ Vg, __half* __restrict__ Og)
{
    extern __shared__ char sm[];
    const uint32_t sb = smem_u32(sm);
    const int tid = threadIdx.x, w = tid >> 5, lane = tid & 31;
    const int bh = blockIdx.y;
    const int t0 = blockIdx.x * 64;
    const int nc = blockIdx.x + 1;

    const int lrow = tid >> 1, lhalf = tid & 1;
    const size_t bhbase = (size_t)bh * T_SEQ;

    {
        const __half* qs = Qg + (bhbase + t0 + lrow) * HD + lhalf * 32;
        const uint32_t qd = sb + lrow * KVROWB + lhalf * 64;
#pragma unroll
        for (int i = 0; i < 4; i++) cp16(qd + i * 16, qs + i * 8);
    }
    {
        const __half* ks = Kg + (bhbase + lrow) * HD + lhalf * 32;
        const __half* vs = Vg + (bhbase + lrow) * HD + lhalf * 32;
        const uint32_t kd = sb + QTILEB + lrow * KVROWB + lhalf * 64;
#pragma unroll
        for (int i = 0; i < 4; i++) {
            cp16(kd + i * 16,          ks + i * 8);
            cp16(kd + QTILEB + i * 16, vs + i * 8);
        }
    }
    cp_commit();

    float o[8][4];
#pragma unroll
    for (int dn = 0; dn < 8; dn++)
#pragma unroll
        for (int t = 0; t < 4; t++) o[dn][t] = 0.f;
    float m1 = -1e30f, m2 = -1e30f, l1 = 0.f, l2 = 0.f;
    uint32_t qf[4][4];

    const int arow  = w * 16 + (lane & 15);
    const int akoff = (lane >> 4) * 8;
    const int brow  = (lane & 7) + ((lane >> 4) << 3);
    const int bkoff = ((lane >> 3) & 1) * 8;
    const int vrowo = (lane & 7) + 8 * ((lane >> 3) & 1);
    const int vcolo = 16 * (lane >> 4);

    for (int c = 0; c < nc; c++) {
        if (c + 1 < nc) {
            const int j0 = (c + 1) * 64;
            const __half* ks = Kg + (bhbase + j0 + lrow) * HD + lhalf * 32;
            const __half* vs = Vg + (bhbase + j0 + lrow) * HD + lhalf * 32;
            const uint32_t kd = sb + QTILEB + ((c + 1) & 1) * KVSTGB + lrow * KVROWB + lhalf * 64;
#pragma unroll
            for (int i = 0; i < 4; i++) {
                cp16(kd + i * 16,          ks + i * 8);
                cp16(kd + QTILEB + i * 16, vs + i * 8);
            }
            cp_commit();
            cp_wait1();
        } else {
            cp_wait0();
        }
        __syncthreads();

        if (c == 0) {
#pragma unroll
            for (int ks = 0; ks < 4; ks++)
                ldsm4(qf[ks], sb + arow * KVROWB + (ks * 16 + akoff) * 2);
        }
        const uint32_t kb = sb + QTILEB + (c & 1) * KVSTGB;
        const uint32_t vb = kb + QTILEB;

        float s[8][4];
#pragma unroll
        for (int nj = 0; nj < 8; nj++)
#pragma unroll
            for (int t = 0; t < 4; t++) s[nj][t] = 0.f;
#pragma unroll
        for (int ks = 0; ks < 4; ks++) {
            uint32_t bK[4][4];
#pragma unroll
            for (int nt = 0; nt < 4; nt++)
                ldsm4(bK[nt], kb + (nt * 16 + brow) * KVROWB + (ks * 16 + bkoff) * 2);
#pragma unroll
            for (int nj = 0; nj < 8; nj++)
                mma16816(s[nj], qf[ks], &bK[nj >> 1][(nj & 1) * 2]);
        }
        const float sc = 0.03125f;  // 1024^-0.5
        if (c == nc - 1) {
            const int r1 = t0 + w * 16 + (lane >> 2);
#pragma unroll
            for (int nj = 0; nj < 8; nj++) {
                const int kvb = t0 + nj * 8 + 2 * (lane & 3);
                s[nj][0] = (kvb     <= r1    ) ? s[nj][0] * sc : -1e30f;
                s[nj][1] = (kvb + 1 <= r1    ) ? s[nj][1] * sc : -1e30f;
                s[nj][2] = (kvb     <= r1 + 8) ? s[nj][2] * sc : -1e30f;
                s[nj][3] = (kvb + 1 <= r1 + 8) ? s[nj][3] * sc : -1e30f;
            }
        } else {
#pragma unroll
            for (int nj = 0; nj < 8; nj++)
#pragma unroll
                for (int t = 0; t < 4; t++) s[nj][t] *= sc;
        }
        float mx1 = -1e30f, mx2 = -1e30f;
#pragma unroll
        for (int nj = 0; nj < 8; nj++) {
            mx1 = fmaxf(mx1, fmaxf(s[nj][0], s[nj][1]));
            mx2 = fmaxf(mx2, fmaxf(s[nj][2], s[nj][3]));
        }
        mx1 = fmaxf(mx1, __shfl_xor_sync(0xffffffffu, mx1, 1));
        mx1 = fmaxf(mx1, __shfl_xor_sync(0xffffffffu, mx1, 2));
        mx2 = fmaxf(mx2, __shfl_xor_sync(0xffffffffu, mx2, 1));
        mx2 = fmaxf(mx2, __shfl_xor_sync(0xffffffffu, mx2, 2));
        const float nm1 = fmaxf(m1, mx1), nm2 = fmaxf(m2, mx2);
        const float cor1 = __expf(m1 - nm1), cor2 = __expf(m2 - nm2);

        float ps1 = 0.f, ps2 = 0.f;
        uint32_t pf[4][4];
#pragma unroll
        for (int kk = 0; kk < 4; kk++) {
#pragma unroll
            for (int hf = 0; hf < 2; hf++) {
                const int nj = kk * 2 + hf;
                const float p0 = __expf(s[nj][0] - nm1);
                const float p1 = __expf(s[nj][1] - nm1);
                const float p2 = __expf(s[nj][2] - nm2);
                const float p3 = __expf(s[nj][3] - nm2);
                ps1 += p0 + p1;
                ps2 += p2 + p3;
                __half2 lo = __floats2half2_rn(p0, p1);
                __half2 hi = __floats2half2_rn(p2, p3);
                pf[kk][hf * 2 + 0] = *reinterpret_cast<uint32_t*>(&lo);
                pf[kk][hf * 2 + 1] = *reinterpret_cast<uint32_t*>(&hi);
            }
        }
        ps1 += __shfl_xor_sync(0xffffffffu, ps1, 1);
        ps1 += __shfl_xor_sync(0xffffffffu, ps1, 2);
        ps2 += __shfl_xor_sync(0xffffffffu, ps2, 1);
        ps2 += __shfl_xor_sync(0xffffffffu, ps2, 2);
        l1 = l1 * cor1 + ps1;
        l2 = l2 * cor2 + ps2;
#pragma unroll
        for (int dn = 0; dn < 8; dn++) {
            o[dn][0] *= cor1; o[dn][1] *= cor1;
            o[dn][2] *= cor2; o[dn][3] *= cor2;
        }
        m1 = nm1; m2 = nm2;

#pragma unroll
        for (int kk = 0; kk < 4; kk++) {
            uint32_t bV[4][4];
            const uint32_t vr = vb + (kk * 16 + vrowo) * KVROWB + vcolo;
#pragma unroll
            for (int d16 = 0; d16 < 4; d16++)
                ldsm4t(bV[d16], vr + d16 * 32);
#pragma unroll
            for (int dn = 0; dn < 8; dn++)
                mma16816(o[dn], pf[kk], &bV[dn >> 1][(dn & 1) * 2]);
        }
        __syncthreads();
    }

    const int b = bh >> 4, h = bh & 15;
    const float i1 = 1.f / l1, i2 = 1.f / l2;
    const int r1 = t0 + w * 16 + (lane >> 2);
    __half* o1 = Og + ((size_t)(b * T_SEQ) + r1) * EMB + h * HD + 2 * (lane & 3);
    __half* o2 = o1 + (size_t)8 * EMB;
#pragma unroll
    for (int dn = 0; dn < 8; dn++) {
        *reinterpret_cast<__half2*>(o1 + dn * 8) =
            __floats2half2_rn(o[dn][0] * i1, o[dn][1] * i1);
        *reinterpret_cast<__half2*>(o2 + dn * 8) =
            __floats2half2_rn(o[dn][2] * i2, o[dn][3] * i2);
    }
}

// -------------------- launch -------------------------------------------------
extern "C" void kernel_launch(void* const* d_in, const int* in_sizes, int n_in,
                              void* d_out, int out_size)
{
    const float* x   = (const float*)d_in[0];
    const float* wq  = (const float*)d_in[1];
    const float* wk  = (const float*)d_in[2];
    const float* wv  = (const float*)d_in[3];
    const float* wo  = (const float*)d_in[4];
    const float* bo  = (const float*)d_in[5];
    const float* g1  = (const float*)d_in[6];
    const float* b1  = (const float*)d_in[7];
    const float* g2  = (const float*)d_in[8];
    const float* b2  = (const float*)d_in[9];
    const float* w1  = (const float*)d_in[10];
    const float* bf1 = (const float*)d_in[11];
    const float* w2  = (const float*)d_in[12];
    const float* bf2 = (const float*)d_in[13];
    float* out = (float*)d_out;

    cudaFuncSetAttribute(mma_gemm<0>, cudaFuncAttributeMaxDynamicSharedMemorySize, GSMEM_BYTES);
    cudaFuncSetAttribute(mma_gemm<1>, cudaFuncAttributeMaxDynamicSharedMemorySize, GSMEM_BYTES);
    cudaFuncSetAttribute(mma_gemm<2>, cudaFuncAttributeMaxDynamicSharedMemorySize, GSMEM_BYTES);
    cudaFuncSetAttribute(attn_mma, cudaFuncAttributeMaxDynamicSharedMemorySize, ATT_SMEM);

    __half *h, *qkv, *at, *h2, *u, *wqkvh, *woh, *w1h, *w2h;
    float *x2;
    cudaGetSymbolAddress((void**)&h,     g_h);
    cudaGetSymbolAddress((void**)&qkv,   g_qkv);
    cudaGetSymbolAddress((void**)&at,    g_at);
    cudaGetSymbolAddress((void**)&x2,    g_x2);
    cudaGetSymbolAddress((void**)&h2,    g_h2);
    cudaGetSymbolAddress((void**)&u,     g_u);
    cudaGetSymbolAddress((void**)&wqkvh, g_wqkv);
    cudaGetSymbolAddress((void**)&woh,   g_wo);
    cudaGetSymbolAddress((void**)&w1h,   g_w1);
    cudaGetSymbolAddress((void**)&w2h,   g_w2);

    // weight prep: transposed fp16 [N,K]; q,k,v stacked into one [3072,1024]
    wtr_kernel<1><<<dim3(EMB / 32, EMB / 32), 256>>>(wq, wqkvh,                 EMB, EMB);
    wtr_kernel<1><<<dim3(EMB / 32, EMB / 32), 256>>>(wk, wqkvh + EMB * EMB,     EMB, EMB);
    wtr_kernel<1><<<dim3(EMB / 32, EMB / 32), 256>>>(wv, wqkvh + 2 * EMB * EMB, EMB, EMB);
    wtr_kernel<0><<<dim3(EMB / 32, EMB / 32), 256>>>(wo, woh, EMB, EMB);
    wtr_kernel<0><<<dim3(FF  / 32, EMB / 32), 256>>>(w1, w1h, EMB, FF);
    wtr_kernel<0><<<dim3(EMB / 32, FF  / 32), 256>>>(w2, w2h, FF,  EMB);

    // LN1 -> fp16
    ln_h_kernel<<<MROWS, 256>>>(x, g1, b1, h);
    // fused QKV projection (N=3072), scatter fp16 to [3][B,H,T,HD]
    mma_gemm<0><<<dim3(3 * EMB / 128, MROWS / 128), 256, GSMEM_BYTES>>>(
        h, wqkvh, nullptr, qkv, nullptr, nullptr, MROWS, 3 * EMB, EMB);
    // tensor-core flash attention -> fp16 [B,T,C]
    attn_mma<<<dim3(T_SEQ / 64, BATCH * HEADS), 128, ATT_SMEM>>>(
        qkv, qkv + MROWS * EMB, qkv + 2 * MROWS * EMB, at);
    // out projection + bias + residual(x) -> x2 fp32
    mma_gemm<1><<<dim3(EMB / 128, MROWS / 128), 256, GSMEM_BYTES>>>(
        at, woh, x2, nullptr, bo, x, MROWS, EMB, EMB);
    // LN2 -> fp16
    ln_h_kernel<<<MROWS, 256>>>(x2, g2, b2, h2);
    // FFN1: relu(h2 @ w1 + bf1) -> fp16
    mma_gemm<2><<<dim3(FF / 128, MROWS / 128), 256, GSMEM_BYTES>>>(
        h2, w1h, nullptr, u, bf1, nullptr, MROWS, FF, EMB);
    // FFN2: u @ w2 + bf2 + x2 -> out fp32
    mma_gemm<1><<<dim3(EMB / 128, MROWS / 128), 256, GSMEM_BYTES>>>(
        u, w2h, out, nullptr, bf2, x2, MROWS, EMB, FF);
}

// round 7
// speedup vs baseline: 5.9011x; 1.3019x over previous
#include <cuda_runtime.h>
#include <cuda_fp16.h>
#include <cstdint>

#define EMB   1024
#define T_SEQ 2048
#define BATCH 2
#define HEADS 16
#define HD    64
#define MROWS (BATCH * T_SEQ)   /* 4096 */
#define FF    (4 * EMB)         /* 4096 */

// -------------------- scratch (static device globals) ----------------------
__device__ __half g_h  [MROWS * EMB];           // LN1 out fp16
__device__ __half g_qkv[3 * MROWS * EMB];       // q,k,v [3][B,H,T,HD]
__device__ __half g_at [MROWS * EMB];           // attention out [B,T,C]
__device__ float  g_x2 [MROWS * EMB];
__device__ __half g_h2 [MROWS * EMB];           // LN2 out fp16
__device__ __half g_u  [MROWS * FF];            // FFN1 out fp16
// transposed fp16 weights [N,K]
__device__ __half g_wqkv[3 * EMB * EMB];
__device__ __half g_wo  [EMB * EMB];
__device__ __half g_w1  [EMB * FF];
__device__ __half g_w2  [FF * EMB];

// -------------------- helpers ----------------------------------------------
__device__ __forceinline__ uint32_t smem_u32(const void* p) {
    uint32_t a;
    asm("{ .reg .u64 t; cvta.to.shared.u64 t, %1; cvt.u32.u64 %0, t; }" : "=r"(a) : "l"(p));
    return a;
}
__device__ __forceinline__ void cp16(uint32_t dst, const void* src) {
    asm volatile("cp.async.cg.shared.global [%0], [%1], 16;" :: "r"(dst), "l"(src) : "memory");
}
__device__ __forceinline__ void cp_commit() {
    asm volatile("cp.async.commit_group;" ::: "memory");
}
__device__ __forceinline__ void ldsm4(uint32_t* r, uint32_t addr) {
    asm volatile("ldmatrix.sync.aligned.m8n8.x4.shared.b16 {%0,%1,%2,%3}, [%4];"
                 : "=r"(r[0]), "=r"(r[1]), "=r"(r[2]), "=r"(r[3]) : "r"(addr));
}
__device__ __forceinline__ void ldsm4t(uint32_t* r, uint32_t addr) {
    asm volatile("ldmatrix.sync.aligned.m8n8.x4.trans.shared.b16 {%0,%1,%2,%3}, [%4];"
                 : "=r"(r[0]), "=r"(r[1]), "=r"(r[2]), "=r"(r[3]) : "r"(addr));
}
__device__ __forceinline__ void mma16816(float* d, const uint32_t* a, const uint32_t* b) {
    asm volatile(
        "mma.sync.aligned.m16n8k16.row.col.f32.f16.f16.f32 "
        "{%0,%1,%2,%3}, {%4,%5,%6,%7}, {%8,%9}, {%0,%1,%2,%3};"
        : "+f"(d[0]), "+f"(d[1]), "+f"(d[2]), "+f"(d[3])
        : "r"(a[0]), "r"(a[1]), "r"(a[2]), "r"(a[3]), "r"(b[0]), "r"(b[1]));
}

// -------------------- LayerNorm row (device fn) ------------------------------
__device__ __forceinline__ void ln_row(
    const float* __restrict__ X, const float* __restrict__ gam,
    const float* __restrict__ bet, __half* __restrict__ Y, int row,
    float* sh_s, float* sh_ss, float* sh_mr)
{
    const int tid = threadIdx.x;
    const float4 v = *reinterpret_cast<const float4*>(X + (size_t)row * EMB + tid * 4);
    float s  = v.x + v.y + v.z + v.w;
    float ss = v.x * v.x + v.y * v.y + v.z * v.z + v.w * v.w;
#pragma unroll
    for (int o = 16; o > 0; o >>= 1) {
        s  += __shfl_xor_sync(0xffffffffu, s,  o);
        ss += __shfl_xor_sync(0xffffffffu, ss, o);
    }
    const int wid = tid >> 5, lid = tid & 31;
    if (lid == 0) { sh_s[wid] = s; sh_ss[wid] = ss; }
    __syncthreads();
    if (tid == 0) {
        float ts = 0.f, tss = 0.f;
#pragma unroll
        for (int i = 0; i < 8; i++) { ts += sh_s[i]; tss += sh_ss[i]; }
        const float mean = ts * (1.0f / EMB);
        const float var  = tss * (1.0f / EMB) - mean * mean;
        sh_mr[0] = mean;
        sh_mr[1] = rsqrtf(var + 1e-5f);
    }
    __syncthreads();
    const float mean = sh_mr[0], r = sh_mr[1];
    const float4 g4 = *reinterpret_cast<const float4*>(gam + tid * 4);
    const float4 b4 = *reinterpret_cast<const float4*>(bet + tid * 4);
    const size_t o = (size_t)row * EMB + tid * 4;
    *reinterpret_cast<__half2*>(Y + o) = __floats2half2_rn(
        (v.x - mean) * r * g4.x + b4.x, (v.y - mean) * r * g4.y + b4.y);
    *reinterpret_cast<__half2*>(Y + o + 2) = __floats2half2_rn(
        (v.z - mean) * r * g4.z + b4.z, (v.w - mean) * r * g4.w + b4.w);
}

// -------------------- LN2 standalone ------------------------------------------
__global__ void __launch_bounds__(256) ln_h_kernel(
    const float* __restrict__ X, const float* __restrict__ gam,
    const float* __restrict__ bet, __half* __restrict__ Y)
{
    __shared__ float sh_s[8], sh_ss[8], sh_mr[2];
    ln_row(X, gam, bet, Y, blockIdx.x, sh_s, sh_ss, sh_mr);
}

// -------------------- fused prep: 6 weight transposes + LN1 ------------------
// blocks [0,12288): weight transpose 32x32 tiles; [12288,16384): LN1 rows.
__global__ void __launch_bounds__(256) prep_kernel(
    const float* __restrict__ wq, const float* __restrict__ wk,
    const float* __restrict__ wv, const float* __restrict__ wo,
    const float* __restrict__ w1, const float* __restrict__ w2,
    const float* __restrict__ x,  const float* __restrict__ g1,
    const float* __restrict__ b1,
    __half* __restrict__ wqkvh, __half* __restrict__ woh,
    __half* __restrict__ w1h,   __half* __restrict__ w2h,
    __half* __restrict__ hout)
{
    __shared__ float tile[32][33];
    const int bid = blockIdx.x;
    if (bid >= 12288) {
        // reuse tile memory for LN reductions
        float* sh_s  = &tile[0][0];
        float* sh_ss = &tile[1][0];
        float* sh_mr = &tile[2][0];
        ln_row(x, g1, b1, hout, bid - 12288, sh_s, sh_ss, sh_mr);
        return;
    }
    const float* W; __half* D; int K, N, MODE, idx;
    if (bid < 3072) {
        const int w = bid >> 10; idx = bid & 1023;
        W = (w == 0) ? wq : (w == 1) ? wk : wv;
        D = wqkvh + (size_t)w * EMB * EMB; K = EMB; N = EMB; MODE = 1;
    } else if (bid < 4096) {
        idx = bid - 3072; W = wo; D = woh; K = EMB; N = EMB; MODE = 0;
    } else if (bid < 8192) {
        idx = bid - 4096; W = w1; D = w1h; K = EMB; N = FF; MODE = 0;
    } else {
        idx = bid - 8192; W = w2; D = w2h; K = FF; N = EMB; MODE = 0;
    }
    const int nblk = N >> 5;
    const int n0 = (idx % nblk) * 32, k0 = (idx / nblk) * 32;
    const int tx = threadIdx.x & 31;
    const int ty = threadIdx.x >> 5;
#pragma unroll
    for (int r = 0; r < 4; r++) {
        const int k = k0 + ty + r * 8;
        const int n = n0 + tx;
        size_t i;
        if (MODE == 0) i = (size_t)k * N + n;
        else           i = (((size_t)(n >> 6) * K + k) << 6) + (n & 63);
        tile[ty + r * 8][tx] = W[i];
    }
    __syncthreads();
#pragma unroll
    for (int r = 0; r < 4; r++) {
        const int n = n0 + ty + r * 8;
        const int k = k0 + tx;
        D[(size_t)n * K + k] = __float2half(tile[tx][ty + r * 8]);
    }
}

// -------------------- mma.sync fp16 GEMM, 4-stage pipeline -------------------
// D[M,N] = A[M,K] * B[N,K]^T.
// EPI 0: fp16 scatter to [3][B,H,T,HD]. EPI 1: +bias +res -> fp32. EPI 2: relu(+bias) -> fp16.
#define RB    80
#define MATB  (128 * RB)        /* 10240 */
#define STGB  (2 * MATB)        /* 20480 */
#define NSTG  4
#define GSMEM_BYTES (NSTG * STGB)   /* 81920 */

template <int EPI>
__global__ void __launch_bounds__(256, 2) mma_gemm(
    const __half* __restrict__ A, const __half* __restrict__ B,
    float* __restrict__ Cf, __half* __restrict__ Chp,
    const float* __restrict__ bias, const float* __restrict__ res,
    int M, int N, int K)
{
    extern __shared__ char smem[];
    const uint32_t sbase = smem_u32(smem);
    const int tid  = threadIdx.x;
    const int wid  = tid >> 5, lane = tid & 31;
    const int m0   = blockIdx.y * 128, n0 = blockIdx.x * 128;
    const int wm   = wid & 3;
    const int wn   = wid >> 2;

    const int lr  = tid & 127;
    const int kg2 = tid >> 7;
    const __half* gA = A + (size_t)(m0 + lr) * K;
    const __half* gB = B + (size_t)(n0 + lr) * K;
    const uint32_t srow = sbase + lr * RB;

    float acc[2][8][4];
#pragma unroll
    for (int i = 0; i < 2; i++)
#pragma unroll
        for (int j = 0; j < 8; j++)
#pragma unroll
            for (int t = 0; t < 4; t++) acc[i][j][t] = 0.f;

    const int NC = K >> 5;

    const int arow  = wm * 32 + (lane & 15);
    const int akoff = (lane >> 4) * 8;
    const int brow  = wn * 64 + (lane & 7) + ((lane >> 4) << 3);
    const int bkoff = ((lane >> 3) & 1) * 8;

    // prologue: chunks 0..2 into stages 0..2
#pragma unroll
    for (int s = 0; s < NSTG - 1; s++) {
        const int k0 = s * 32;
        const uint32_t sd = srow + s * STGB;
#pragma unroll
        for (int g = 0; g < 2; g++) {
            const int kg = kg2 * 2 + g;
            cp16(sd + kg * 16,        gA + k0 + kg * 8);
            cp16(sd + MATB + kg * 16, gB + k0 + kg * 8);
        }
        cp_commit();
    }

    for (int c = 0; c < NC; c++) {
        asm volatile("cp.async.wait_group %0;" :: "n"(NSTG - 2) : "memory");
        __syncthreads();
        // issue chunk c+3 into stage (c+3)%4 == stage computed at iter c-1 (barrier-protected)
        if (c + NSTG - 1 < NC) {
            const int k0 = (c + NSTG - 1) * 32;
            const uint32_t sd = srow + ((c + NSTG - 1) & (NSTG - 1)) * STGB;
#pragma unroll
            for (int g = 0; g < 2; g++) {
                const int kg = kg2 * 2 + g;
                cp16(sd + kg * 16,        gA + k0 + kg * 8);
                cp16(sd + MATB + kg * 16, gB + k0 + kg * 8);
            }
        }
        cp_commit();

        const uint32_t sb = sbase + (c & (NSTG - 1)) * STGB;
#pragma unroll
        for (int ks = 0; ks < 2; ks++) {
            uint32_t af[2][4], bf[4][4];
#pragma unroll
            for (int mi = 0; mi < 2; mi++)
                ldsm4(af[mi], sb + (arow + mi * 16) * RB + (ks * 16 + akoff) * 2);
#pragma unroll
            for (int nt = 0; nt < 4; nt++)
                ldsm4(bf[nt], sb + MATB + (brow + nt * 16) * RB + (ks * 16 + bkoff) * 2);
#pragma unroll
            for (int mi = 0; mi < 2; mi++)
#pragma unroll
                for (int nj = 0; nj < 8; nj++)
                    mma16816(acc[mi][nj], af[mi], &bf[nj >> 1][(nj & 1) * 2]);
        }
    }

    // epilogue
    const int mrow = m0 + wm * 32 + (lane >> 2);
    const int ncol = n0 + wn * 64 + (lane & 3) * 2;
#pragma unroll
    for (int mi = 0; mi < 2; mi++)
#pragma unroll
        for (int nj = 0; nj < 8; nj++)
#pragma unroll
            for (int hf = 0; hf < 2; hf++) {
                const int m = mrow + mi * 16 + hf * 8;
                const int n = ncol + nj * 8;
                float v0 = acc[mi][nj][hf * 2 + 0];
                float v1 = acc[mi][nj][hf * 2 + 1];
                if (EPI == 0) {
                    const int mat = n >> 10, hh = (n >> 6) & 15, d = n & 63;
                    const int bb = m >> 11, t = m & 2047;
                    *reinterpret_cast<__half2*>(
                        Chp + (size_t)mat * (MROWS * EMB) +
                        (((size_t)(bb * HEADS + hh)) * T_SEQ + t) * HD + d) =
                        __floats2half2_rn(v0, v1);
                } else if (EPI == 1) {
                    const size_t base = (size_t)m * N + n;
                    const float2 bs = *reinterpret_cast<const float2*>(bias + n);
                    const float2 rs = *reinterpret_cast<const float2*>(res + base);
                    *reinterpret_cast<float2*>(Cf + base) =
                        make_float2(v0 + bs.x + rs.x, v1 + bs.y + rs.y);
                } else {
                    const size_t base = (size_t)m * N + n;
                    const float2 bs = *reinterpret_cast<const float2*>(bias + n);
                    *reinterpret_cast<__half2*>(Chp + base) =
                        __floats2half2_rn(fmaxf(v0 + bs.x, 0.f), fmaxf(v1 + bs.y, 0.f));
                }
            }
}

// -------------------- tensor-core causal flash attention (fp16) -------------
#define KVROWB 144
#define QTILEB (64 * KVROWB)
#define KVSTGB (2 * QTILEB)
#define ATT_SMEM (QTILEB + 2 * KVSTGB)

__global__ void __launch_bounds__(128) attn_mma(
    const __half* __restrict__ Qg, const __half* __restrict__ Kg,
    const __half* __restrict__ Vg, __half* __restrict__ Og)
{
    extern __shared__ char sm[];
    const uint32_t sb = smem_u32(sm);
    const int tid = threadIdx.x, w = tid >> 5, lane = tid & 31;
    const int bh = blockIdx.y;
    const int t0 = blockIdx.x * 64;
    const int nc = blockIdx.x + 1;

    const int lrow = tid >> 1, lhalf = tid & 1;
    const size_t bhbase = (size_t)bh * T_SEQ;

    {
        const __half* qs = Qg + (bhbase + t0 + lrow) * HD + lhalf * 32;
        const uint32_t qd = sb + lrow * KVROWB + lhalf * 64;
#pragma unroll
        for (int i = 0; i < 4; i++) cp16(qd + i * 16, qs + i * 8);
    }
    {
        const __half* ks = Kg + (bhbase + lrow) * HD + lhalf * 32;
        const __half* vs = Vg + (bhbase + lrow) * HD + lhalf * 32;
        const uint32_t kd = sb + QTILEB + lrow * KVROWB + lhalf * 64;
#pragma unroll
        for (int i = 0; i < 4; i++) {
            cp16(kd + i * 16,          ks + i * 8);
            cp16(kd + QTILEB + i * 16, vs + i * 8);
        }
    }
    cp_commit();

    float o[8][4];
#pragma unroll
    for (int dn = 0; dn < 8; dn++)
#pragma unroll
        for (int t = 0; t < 4; t++) o[dn][t] = 0.f;
    float m1 = -1e30f, m2 = -1e30f, l1 = 0.f, l2 = 0.f;
    uint32_t qf[4][4];

    const int arow  = w * 16 + (lane & 15);
    const int akoff = (lane >> 4) * 8;
    const int brow  = (lane & 7) + ((lane >> 4) << 3);
    const int bkoff = ((lane >> 3) & 1) * 8;
    const int vrowo = (lane & 7) + 8 * ((lane >> 3) & 1);
    const int vcolo = 16 * (lane >> 4);

    for (int c = 0; c < nc; c++) {
        if (c + 1 < nc) {
            const int j0 = (c + 1) * 64;
            const __half* ks = Kg + (bhbase + j0 + lrow) * HD + lhalf * 32;
            const __half* vs = Vg + (bhbase + j0 + lrow) * HD + lhalf * 32;
            const uint32_t kd = sb + QTILEB + ((c + 1) & 1) * KVSTGB + lrow * KVROWB + lhalf * 64;
#pragma unroll
            for (int i = 0; i < 4; i++) {
                cp16(kd + i * 16,          ks + i * 8);
                cp16(kd + QTILEB + i * 16, vs + i * 8);
            }
            cp_commit();
            asm volatile("cp.async.wait_group 1;" ::: "memory");
        } else {
            asm volatile("cp.async.wait_group 0;" ::: "memory");
        }
        __syncthreads();

        if (c == 0) {
#pragma unroll
            for (int ks = 0; ks < 4; ks++)
                ldsm4(qf[ks], sb + arow * KVROWB + (ks * 16 + akoff) * 2);
        }
        const uint32_t kb = sb + QTILEB + (c & 1) * KVSTGB;
        const uint32_t vb = kb + QTILEB;

        float s[8][4];
#pragma unroll
        for (int nj = 0; nj < 8; nj++)
#pragma unroll
            for (int t = 0; t < 4; t++) s[nj][t] = 0.f;
#pragma unroll
        for (int ks = 0; ks < 4; ks++) {
            uint32_t bK[4][4];
#pragma unroll
            for (int nt = 0; nt < 4; nt++)
                ldsm4(bK[nt], kb + (nt * 16 + brow) * KVROWB + (ks * 16 + bkoff) * 2);
#pragma unroll
            for (int nj = 0; nj < 8; nj++)
                mma16816(s[nj], qf[ks], &bK[nj >> 1][(nj & 1) * 2]);
        }
        const float sc = 0.03125f;  // 1024^-0.5
        if (c == nc - 1) {
            const int r1 = t0 + w * 16 + (lane >> 2);
#pragma unroll
            for (int nj = 0; nj < 8; nj++) {
                const int kvb = t0 + nj * 8 + 2 * (lane & 3);
                s[nj][0] = (kvb     <= r1    ) ? s[nj][0] * sc : -1e30f;
                s[nj][1] = (kvb + 1 <= r1    ) ? s[nj][1] * sc : -1e30f;
                s[nj][2] = (kvb     <= r1 + 8) ? s[nj][2] * sc : -1e30f;
                s[nj][3] = (kvb + 1 <= r1 + 8) ? s[nj][3] * sc : -1e30f;
            }
        } else {
#pragma unroll
            for (int nj = 0; nj < 8; nj++)
#pragma unroll
                for (int t = 0; t < 4; t++) s[nj][t] *= sc;
        }
        float mx1 = -1e30f, mx2 = -1e30f;
#pragma unroll
        for (int nj = 0; nj < 8; nj++) {
            mx1 = fmaxf(mx1, fmaxf(s[nj][0], s[nj][1]));
            mx2 = fmaxf(mx2, fmaxf(s[nj][2], s[nj][3]));
        }
        mx1 = fmaxf(mx1, __shfl_xor_sync(0xffffffffu, mx1, 1));
        mx1 = fmaxf(mx1, __shfl_xor_sync(0xffffffffu, mx1, 2));
        mx2 = fmaxf(mx2, __shfl_xor_sync(0xffffffffu, mx2, 1));
        mx2 = fmaxf(mx2, __shfl_xor_sync(0xffffffffu, mx2, 2));
        const float nm1 = fmaxf(m1, mx1), nm2 = fmaxf(m2, mx2);
        const float cor1 = __expf(m1 - nm1), cor2 = __expf(m2 - nm2);

        float ps1 = 0.f, ps2 = 0.f;
        uint32_t pf[4][4];
#pragma unroll
        for (int kk = 0; kk < 4; kk++) {
#pragma unroll
            for (int hf = 0; hf < 2; hf++) {
                const int nj = kk * 2 + hf;
                const float p0 = __expf(s[nj][0] - nm1);
                const float p1 = __expf(s[nj][1] - nm1);
                const float p2 = __expf(s[nj][2] - nm2);
                const float p3 = __expf(s[nj][3] - nm2);
                ps1 += p0 + p1;
                ps2 += p2 + p3;
                __half2 lo = __floats2half2_rn(p0, p1);
                __half2 hi = __floats2half2_rn(p2, p3);
                pf[kk][hf * 2 + 0] = *reinterpret_cast<uint32_t*>(&lo);
                pf[kk][hf * 2 + 1] = *reinterpret_cast<uint32_t*>(&hi);
            }
        }
        ps1 += __shfl_xor_sync(0xffffffffu, ps1, 1);
        ps1 += __shfl_xor_sync(0xffffffffu, ps1, 2);
        ps2 += __shfl_xor_sync(0xffffffffu, ps2, 1);
        ps2 += __shfl_xor_sync(0xffffffffu, ps2, 2);
        l1 = l1 * cor1 + ps1;
        l2 = l2 * cor2 + ps2;
#pragma unroll
        for (int dn = 0; dn < 8; dn++) {
            o[dn][0] *= cor1; o[dn][1] *= cor1;
            o[dn][2] *= cor2; o[dn][3] *= cor2;
        }
        m1 = nm1; m2 = nm2;

#pragma unroll
        for (int kk = 0; kk < 4; kk++) {
            uint32_t bV[4][4];
            const uint32_t vr = vb + (kk * 16 + vrowo) * KVROWB + vcolo;
#pragma unroll
            for (int d16 = 0; d16 < 4; d16++)
                ldsm4t(bV[d16], vr + d16 * 32);
#pragma unroll
            for (int dn = 0; dn < 8; dn++)
                mma16816(o[dn], pf[kk], &bV[dn >> 1][(dn & 1) * 2]);
        }
        __syncthreads();
    }

    const int b = bh >> 4, h = bh & 15;
    const float i1 = 1.f / l1, i2 = 1.f / l2;
    const int r1 = t0 + w * 16 + (lane >> 2);
    __half* o1 = Og + ((size_t)(b * T_SEQ) + r1) * EMB + h * HD + 2 * (lane & 3);
    __half* o2 = o1 + (size_t)8 * EMB;
#pragma unroll
    for (int dn = 0; dn < 8; dn++) {
        *reinterpret_cast<__half2*>(o1 + dn * 8) =
            __floats2half2_rn(o[dn][0] * i1, o[dn][1] * i1);
        *reinterpret_cast<__half2*>(o2 + dn * 8) =
            __floats2half2_rn(o[dn][2] * i2, o[dn][3] * i2);
    }
}

// -------------------- launch -------------------------------------------------
extern "C" void kernel_launch(void* const* d_in, const int* in_sizes, int n_in,
                              void* d_out, int out_size)
{
    const float* x   = (const float*)d_in[0];
    const float* wq  = (const float*)d_in[1];
    const float* wk  = (const float*)d_in[2];
    const float* wv  = (const float*)d_in[3];
    const float* wo  = (const float*)d_in[4];
    const float* bo  = (const float*)d_in[5];
    const float* g1  = (const float*)d_in[6];
    const float* b1  = (const float*)d_in[7];
    const float* g2  = (const float*)d_in[8];
    const float* b2  = (const float*)d_in[9];
    const float* w1  = (const float*)d_in[10];
    const float* bf1 = (const float*)d_in[11];
    const float* w2  = (const float*)d_in[12];
    const float* bf2 = (const float*)d_in[13];
    float* out = (float*)d_out;

    cudaFuncSetAttribute(mma_gemm<0>, cudaFuncAttributeMaxDynamicSharedMemorySize, GSMEM_BYTES);
    cudaFuncSetAttribute(mma_gemm<1>, cudaFuncAttributeMaxDynamicSharedMemorySize, GSMEM_BYTES);
    cudaFuncSetAttribute(mma_gemm<2>, cudaFuncAttributeMaxDynamicSharedMemorySize, GSMEM_BYTES);
    cudaFuncSetAttribute(attn_mma, cudaFuncAttributeMaxDynamicSharedMemorySize, ATT_SMEM);

    __half *h, *qkv, *at, *h2, *u, *wqkvh, *woh, *w1h, *w2h;
    float *x2;
    cudaGetSymbolAddress((void**)&h,     g_h);
    cudaGetSymbolAddress((void**)&qkv,   g_qkv);
    cudaGetSymbolAddress((void**)&at,    g_at);
    cudaGetSymbolAddress((void**)&x2,    g_x2);
    cudaGetSymbolAddress((void**)&h2,    g_h2);
    cudaGetSymbolAddress((void**)&u,     g_u);
    cudaGetSymbolAddress((void**)&wqkvh, g_wqkv);
    cudaGetSymbolAddress((void**)&woh,   g_wo);
    cudaGetSymbolAddress((void**)&w1h,   g_w1);
    cudaGetSymbolAddress((void**)&w2h,   g_w2);

    // 1: fused prep (6 weight transposes + LN1)
    prep_kernel<<<16384, 256>>>(wq, wk, wv, wo, w1, w2, x, g1, b1,
                                wqkvh, woh, w1h, w2h, h);
    // 2: fused QKV projection (N=3072), scatter fp16 to [3][B,H,T,HD]
    mma_gemm<0><<<dim3(3 * EMB / 128, MROWS / 128), 256, GSMEM_BYTES>>>(
        h, wqkvh, nullptr, qkv, nullptr, nullptr, MROWS, 3 * EMB, EMB);
    // 3: tensor-core flash attention -> fp16 [B,T,C]
    attn_mma<<<dim3(T_SEQ / 64, BATCH * HEADS), 128, ATT_SMEM>>>(
        qkv, qkv + MROWS * EMB, qkv + 2 * MROWS * EMB, at);
    // 4: out projection + bias + residual(x) -> x2 fp32
    mma_gemm<1><<<dim3(EMB / 128, MROWS / 128), 256, GSMEM_BYTES>>>(
        at, woh, x2, nullptr, bo, x, MROWS, EMB, EMB);
    // 5: LN2 -> fp16
    ln_h_kernel<<<MROWS, 256>>>(x2, g2, b2, h2);
    // 6: FFN1: relu(h2 @ w1 + bf1) -> fp16   (profiled launch)
    mma_gemm<2><<<dim3(FF / 128, MROWS / 128), 256, GSMEM_BYTES>>>(
        h2, w1h, nullptr, u, bf1, nullptr, MROWS, FF, EMB);
    // 7: FFN2: u @ w2 + bf2 + x2 -> out fp32
    mma_gemm<1><<<dim3(EMB / 128, MROWS / 128), 256, GSMEM_BYTES>>>(
        u, w2h, out, nullptr, bf2, x2, MROWS, EMB, FF);
}